// round 12
// baseline (speedup 1.0000x reference)
#include <cuda_runtime.h>
#include <cuda_fp16.h>
#include <stdint.h>

#define Bz 4
#define Nn 4096
#define Mm 4096
#define Cc 256
#define RSTRIDE 768

#define BIG2 1.0e9f
__device__ __constant__ float c_NEG_INV2 = (float)(-1.0 / 0.01000001 * 1.4426950408889634);

// ---------------- persistent device scratch ----------------
__device__ __align__(16) float2 g_sl0[Bz][Nn];
__device__ __align__(16) float2 g_tl0[Bz][Mm];
__device__ unsigned char g_sok0[Bz][Nn];
__device__ int g_tkey[Bz][Mm];
__device__ int g_skey[Bz][Nn];
__device__ int g_tperm[Bz][Mm];
__device__ int g_sperm[Bz][Nn];

__device__ __align__(16) float4 g_sv4[Bz][Nn];
__device__ __align__(16) float4 g_tu4[Bz][Mm];
__device__ unsigned char g_sok[Bz][Nn];
__device__ unsigned char g_has[Bz][Mm];
__device__ __align__(16) float4 g_sbb[Bz][Nn / 32];
__device__ __align__(16) float4 g_tbb[Bz][Mm / 32];

__device__ float g_u2[Bz][Mm];
__device__ float g_v2[Bz][Nn];
__device__ __align__(16) float g_eu[Bz][Mm];
__device__ __align__(16) float g_ev[Bz][Nn];
__device__ int g_cnt0u[3 * Bz];
__device__ int g_cnt0v[3 * Bz];

__device__ __align__(16) unsigned short g_colT[Bz][Mm * RSTRIDE];
__device__ __align__(16) unsigned short g_colS[Bz][Nn * RSTRIDE];
__device__ __align__(16) float g_valT[Bz][Mm * RSTRIDE];
__device__ __align__(16) float g_valS[Bz][Nn * RSTRIDE];
__device__ int g_nnzT[Bz][Mm];
__device__ int g_nnzS[Bz][Nn];

__device__ __align__(16) __half g_fT[Bz][Cc][Nn];

// ---------------- mask dtype auto-detect ------------------------------------
__device__ __forceinline__ int detect_fmt(const unsigned* w) {
    bool sawF = false, sawU = false;
    for (int i = 0; i < 64; i++) {
        unsigned v = w[i];
        if (v == 0x3F800000u) sawF = true;
        else if (v > 1u) {
            unsigned b0 = v & 255u, b1 = (v >> 8) & 255u, b2 = (v >> 16) & 255u, b3 = v >> 24;
            if (b0 <= 1u && b1 <= 1u && b2 <= 1u && b3 <= 1u) sawU = true;
            else sawF = true;
        }
    }
    if (sawF) return 2;
    if (sawU) return 0;
    return 1;
}
__device__ __forceinline__ bool read_mask(const void* p, int i, int fmt) {
    if (fmt == 0) return ((const unsigned char*)p)[i] != 0;
    if (fmt == 1) return ((const int*)p)[i] != 0;
    return ((const float*)p)[i] != 0.0f;
}

__device__ __forceinline__ unsigned spread4(unsigned x) {
    x &= 15u; x = (x | (x << 2)) & 0x33u; x = (x | (x << 1)) & 0x55u; return x;
}
__device__ __forceinline__ int morton_key(float x, float y) {
    int cx = (int)(x * 16.0f); cx = cx < 0 ? 0 : (cx > 15 ? 15 : cx);
    int cy = (int)(y * 16.0f); cy = cy < 0 ? 0 : (cy > 15 ? 15 : cy);
    return (int)(spread4((unsigned)cx) | (spread4((unsigned)cy) << 1));
}

// ---------------- prep -------------------------------------------------------
__global__ void prep_kernel(const float* __restrict__ slocs,
                            const float* __restrict__ tlocs,
                            const void* __restrict__ smask,
                            const void* __restrict__ tmask) {
    __shared__ int sf[2];
    if (threadIdx.x == 0) {
        sf[0] = detect_fmt((const unsigned*)smask);
        sf[1] = detect_fmt((const unsigned*)tmask);
    }
    __syncthreads();
    int i = blockIdx.x * blockDim.x + threadIdx.x;
    if (blockIdx.x == 0 && threadIdx.x < 3 * Bz) {
        g_cnt0u[threadIdx.x] = 0;
        g_cnt0v[threadIdx.x] = 0;
    }
    if (i >= Bz * Nn) return;
    int b = i / Nn, n = i % Nn;

    bool sok = read_mask(smask, i, sf[0]);
    float sx = slocs[2 * i], sy = slocs[2 * i + 1];
    g_sl0[b][n] = make_float2(sok ? sx : -1e18f, sy);
    g_sok0[b][n] = sok ? 1 : 0;
    g_skey[b][n] = sok ? morton_key(sx, sy) : 256;
    g_v2[b][n] = 0.0f;
    g_ev[b][n] = 1.0f;

    bool tok = read_mask(tmask, i, sf[1]);
    float tx = tlocs[2 * i], ty = tlocs[2 * i + 1];
    g_tl0[b][n] = make_float2(tok ? tx : 1e18f, ty);
    g_tkey[b][n] = tok ? morton_key(tx, ty) : 256;
}

// ---------------- stable counting sort + scatter + bboxes ---------------------
// grid (2, Bz); block 1024 = 32 warps; warp w owns elements [w*128, w*128+128)
__global__ __launch_bounds__(1024) void sort_scatter_kernel() {
    __shared__ int hist[32][257];            // per-warp per-cell counts -> warp bases
    __shared__ int cellbase[258];
    __shared__ unsigned short ranks[4096];
    const int side = blockIdx.x, b = blockIdx.y, tid = threadIdx.x;
    const int warp = tid >> 5, lane = tid & 31;
    const unsigned FULL = 0xffffffffu;

    for (int i = tid; i < 32 * 257; i += 1024) (&hist[0][0])[i] = 0;
    __syncthreads();

    // phase 1: stable per-warp ranks (rounds in index order; within round by lane)
    #pragma unroll
    for (int r = 0; r < 4; r++) {
        int i = warp * 128 + r * 32 + lane;
        int cell = side ? g_skey[b][i] : g_tkey[b][i];
        unsigned peers = __match_any_sync(FULL, cell);
        int leader = __ffs(peers) - 1;
        int rankin = __popc(peers & ((1u << lane) - 1u));
        int old = 0;
        if (lane == leader) old = atomicAdd(&hist[warp][cell], __popc(peers));
        old = __shfl_sync(FULL, old, leader);
        ranks[i] = (unsigned short)(old + rankin);
    }
    __syncthreads();

    // phase 2: per-cell warp prefix (hist becomes warp base), cell totals
    for (int c = tid; c < 257; c += 1024) {
        int run = 0;
        #pragma unroll
        for (int w = 0; w < 32; w++) {
            int t = hist[w][c];
            hist[w][c] = run;
            run += t;
        }
        cellbase[c + 1] = run;
    }
    __syncthreads();
    if (tid == 0) {
        cellbase[0] = 0;
        for (int c = 1; c <= 257; c++) cellbase[c] += cellbase[c - 1];
    }
    __syncthreads();

    // phase 3: scatter to sorted order
    #pragma unroll
    for (int r = 0; r < 4; r++) {
        int i = warp * 128 + r * 32 + lane;
        int cell = side ? g_skey[b][i] : g_tkey[b][i];
        int pos = cellbase[cell] + hist[warp][cell] + (int)ranks[i];
        if (side) {
            float2 p = g_sl0[b][i];
            g_sv4[b][pos] = make_float4(p.x, p.y, 0.0f, 0.0f);
            g_sok[b][pos] = g_sok0[b][i];
            g_sperm[b][pos] = i;
        } else {
            float2 p = g_tl0[b][i];
            g_tu4[b][pos] = make_float4(p.x, p.y, 0.0f, 0.0f);
            g_tperm[b][pos] = i;
        }
    }
    __syncthreads();   // makes this block's gmem writes visible block-wide

    // phase 4: 32-pt chunk bboxes over sorted coords
    for (int i = tid; i < 4096; i += 1024) {
        float4 p4 = side ? g_sv4[b][i] : g_tu4[b][i];
        float mnx = p4.x, mxx = p4.x, mny = p4.y, mxy = p4.y;
        #pragma unroll
        for (int off = 16; off; off >>= 1) {
            mnx = fminf(mnx, __shfl_xor_sync(FULL, mnx, off));
            mxx = fmaxf(mxx, __shfl_xor_sync(FULL, mxx, off));
            mny = fminf(mny, __shfl_xor_sync(FULL, mny, off));
            mxy = fmaxf(mxy, __shfl_xor_sync(FULL, mxy, off));
        }
        if (lane == 0) {
            int chunk = i >> 5;
            float4 bb = make_float4(mnx, mny, mxx, mxy);
            if (side) g_sbb[b][chunk] = bb; else g_tbb[b][chunk] = bb;
        }
    }
}

// ---------------- build padded CSR (cols + K f32) once ------------------------
__global__ __launch_bounds__(256) void csr_build() {
    const int b = blockIdx.y, side = blockIdx.z;
    const int warp = threadIdx.x >> 5, lane = threadIdx.x & 31;
    const int row = blockIdx.x * 8 + warp;
    const unsigned FULL = 0xffffffffu;
    const float NEG_INV2 = c_NEG_INV2;

    float4 rp = (side == 0) ? g_tu4[b][row] : g_sv4[b][row];
    const float4* opp = (side == 0) ? g_sv4[b] : g_tu4[b];
    const float4* bb  = (side == 0) ? g_sbb[b] : g_tbb[b];
    unsigned short* cseg = ((side == 0) ? g_colT[b] : g_colS[b]) + (size_t)row * RSTRIDE;
    float*          vseg = ((side == 0) ? g_valT[b] : g_valS[b]) + (size_t)row * RSTRIDE;

    int cnt = 0;
    #pragma unroll
    for (int t = 0; t < 4; t++) {
        int c = t * 32 + lane;
        float4 cb = bb[c];
        float ddx = fmaxf(fmaxf(cb.x - rp.x, rp.x - cb.z), 0.0f);
        float ddy = fmaxf(fmaxf(cb.y - rp.y, rp.y - cb.w), 0.0f);
        bool inc = (ddx * ddx + ddy * ddy < 0.0401f);
        unsigned mask = __ballot_sync(FULL, inc);
        while (mask) {
            int chunk = t * 32 + (__ffs(mask) - 1);
            mask &= mask - 1;
            int col = chunk * 32 + lane;
            float4 q = opp[col];
            float dx = __fadd_rn(rp.x, -q.x);
            float dy = __fadd_rn(rp.y, -q.y);
            float d2 = __fadd_rn(__fmul_rn(dx, dx), __fmul_rn(dy, dy));
            bool valid = (d2 < 0.04f);
            unsigned vm = __ballot_sync(FULL, valid);
            if (valid) {
                int slot = cnt + __popc(vm & ((1u << lane) - 1u));
                if (slot < RSTRIDE) {
                    cseg[slot] = (unsigned short)col;
                    vseg[slot] = exp2f(__fmul_rn(d2, NEG_INV2));
                }
            }
            cnt += __popc(vm);
        }
    }
    if (lane == 0) {
        cnt = cnt > RSTRIDE ? RSTRIDE : cnt;
        if (side == 0) { g_nnzT[b][row] = cnt; g_has[b][row] = (cnt > 0) ? 1 : 0; }
        else           { g_nnzS[b][row] = cnt; }
    }
}

// ---------------- LSE pass: FMA stream over SoA CSR (R9 form) -----------------
template <int MODE>
__global__ __launch_bounds__(256) void lse_kernel(int iter) {
    const int b = blockIdx.y;
    const int warp = threadIdx.x >> 5, lane = threadIdx.x & 31;
    const int row = blockIdx.x * 8 + warp;
    const unsigned FULL = 0xffffffffu;

    const unsigned short* cseg = ((MODE == 0) ? g_colT[b] : g_colS[b]) + (size_t)row * RSTRIDE;
    const float*          vseg = ((MODE == 0) ? g_valT[b] : g_valS[b]) + (size_t)row * RSTRIDE;
    const float*          ed   = (MODE == 0) ? g_ev[b] : g_eu[b];
    const int cnt = (MODE == 0) ? g_nnzT[b][row] : g_nnzS[b][row];

    float s0 = 0.0f, s1 = 0.0f;
    int i = 2 * lane;
    for (; i + 1 < cnt; i += 64) {
        unsigned cc = *(const unsigned*)(cseg + i);
        float2 kk = *(const float2*)(vseg + i);
        s0 = __fmaf_rn(kk.x, ed[cc & 0xFFFFu], s0);
        s1 = __fmaf_rn(kk.y, ed[cc >> 16], s1);
    }
    if (i < cnt) s0 = __fmaf_rn(vseg[i], ed[cseg[i]], s0);

    float s = s0 + s1;
    #pragma unroll
    for (int off = 16; off; off >>= 1) s += __shfl_xor_sync(FULL, s, off);

    if (lane == 0) {
        if (MODE == 0) {
            float tot = s + ((iter > 0) ? (float)g_cnt0v[(iter - 1) * Bz + b] : 0.0f);
            float u2;
            if (tot > 0.0f) u2 = -log2f(tot);
            else { u2 = BIG2; atomicAdd(&g_cnt0u[iter * Bz + b], 1); }
            g_u2[b][row] = u2;
            g_eu[b][row] = (tot > 0.0f) ? exp2f(u2) : 1.0f;
        } else {
            float tot = s + (float)g_cnt0u[iter * Bz + b];
            bool sok = g_sok[b][row] != 0;
            float v2;
            if (tot > 0.0f) v2 = -log2f(tot);
            else { v2 = BIG2; if (sok) atomicAdd(&g_cnt0v[iter * Bz + b], 1); }
            v2 = sok ? v2 : 0.0f;
            g_v2[b][row] = v2;
            g_ev[b][row] = (tot > 0.0f || !sok) ? exp2f(v2) : 1.0f;
        }
    }
}

// ---------------- feats f32 [b][orig n][c] -> fp16 [b][c][sorted n] ----------
__global__ void feats_transpose(const float* __restrict__ f) {
    __shared__ float tile[32][33];
    int b = blockIdx.z;
    int n0 = blockIdx.x * 32, c0 = blockIdx.y * 32;
    int tx = threadIdx.x, ty = threadIdx.y;
    #pragma unroll
    for (int j = 0; j < 4; j++) {
        int n = n0 + ty + j * 8;
        int on = g_sperm[b][n];
        tile[ty + j * 8][tx] = f[((b * Nn + on) * Cc) + (c0 + tx)];
    }
    __syncthreads();
    #pragma unroll
    for (int j = 0; j < 4; j++) {
        int c = c0 + ty + j * 8;
        g_fT[b][c][n0 + tx] = __float2half(tile[tx][ty + j * 8]);
    }
}

// ---------------- fused attn-recompute GEMM (full-C blocks) ------------------
__device__ __forceinline__ void mma16816(float& c0, float& c1, float& c2, float& c3,
                                         unsigned a0, unsigned a1, unsigned a2, unsigned a3,
                                         unsigned b0, unsigned b1) {
    asm volatile(
        "mma.sync.aligned.m16n8k16.row.col.f32.f16.f16.f32 "
        "{%0,%1,%2,%3}, {%4,%5,%6,%7}, {%8,%9}, {%0,%1,%2,%3};\n"
        : "+f"(c0), "+f"(c1), "+f"(c2), "+f"(c3)
        : "r"(a0), "r"(a1), "r"(a2), "r"(a3), "r"(b0), "r"(b1));
}

__device__ __forceinline__ float attn_val(float txx, float tyy, float uu2, float4 q) {
    float dx = __fadd_rn(txx, -q.x);
    float dy = __fadd_rn(tyy, -q.y);
    float d2 = __fadd_rn(__fmul_rn(dx, dx), __fmul_rn(dy, dy));
    if (d2 < 0.04f)
        return exp2f(__fadd_rn(__fmaf_rn(d2, c_NEG_INV2, uu2), q.z));
    return 0.0f;
}

__device__ __forceinline__ unsigned pack2(float x, float y) {
    __half2 h = __floats2half2_rn(x, y);
    return *reinterpret_cast<unsigned*>(&h);
}

#define GBM 64
#define GBK 64
#define SBSTRIDE 72

// 256 threads = 8 warps = 4 m-groups x 2 c-halves (128c each); grid (64, Bz)
__global__ __launch_bounds__(256) void gemm_kernel(float* __restrict__ out) {
    const int b  = blockIdx.y;
    const int m0 = blockIdx.x * GBM;
    const int warp = threadIdx.x >> 5, lane = threadIdx.x & 31;
    const int mg = warp >> 1, chalf = warp & 1;
    const int gid = lane >> 2, tig = lane & 3;

    __shared__ __align__(16) __half sB[Cc][SBSTRIDE];   // 256 x 72 halves = 36KB
    __shared__ __align__(16) float4 sS[GBK];

    float tmnx, tmxx, tmny, tmxy;
    {
        float4 b0 = g_tbb[b][(m0 >> 5) + 0], b1 = g_tbb[b][(m0 >> 5) + 1];
        tmnx = fminf(b0.x, b1.x); tmny = fminf(b0.y, b1.y);
        tmxx = fmaxf(b0.z, b1.z); tmxy = fmaxf(b0.w, b1.w);
    }

    const int rlo = m0 + mg * 16 + gid;
    const int rhi = rlo + 8;
    float4 plo = g_tu4[b][rlo]; plo.z = g_u2[b][rlo];
    float4 phi = g_tu4[b][rhi]; phi.z = g_u2[b][rhi];
    const bool haslo = g_has[b][rlo] != 0;
    const bool hashi = g_has[b][rhi] != 0;

    float acc[16][4];
    #pragma unroll
    for (int j = 0; j < 16; j++) {
        acc[j][0] = 0.f; acc[j][1] = 0.f; acc[j][2] = 0.f; acc[j][3] = 0.f;
    }

    for (int n0 = 0; n0 < Nn; n0 += GBK) {
        {
            float4 s0 = g_sbb[b][(n0 >> 5) + 0], s1 = g_sbb[b][(n0 >> 5) + 1];
            float smnx = fminf(s0.x, s1.x), smny = fminf(s0.y, s1.y);
            float smxx = fmaxf(s0.z, s1.z), smxy = fmaxf(s0.w, s1.w);
            float ddx = fmaxf(fmaxf(smnx - tmxx, tmnx - smxx), 0.0f);
            float ddy = fmaxf(fmaxf(smny - tmxy, tmny - smxy), 0.0f);
            if (ddx * ddx + ddy * ddy >= 0.0401f) continue;
        }
        __syncthreads();
        {
            int idx = threadIdx.x;                 // 256 threads, 2048 uint4
            #pragma unroll
            for (int t = 0; t < 8; t++, idx += 256) {
                int row = idx >> 3, ch8 = idx & 7;
                const uint4* src = reinterpret_cast<const uint4*>(&g_fT[b][row][n0]) + ch8;
                *reinterpret_cast<uint4*>(&sB[row][ch8 * 8]) = *src;
            }
        }
        if (threadIdx.x < GBK) {
            int n = n0 + threadIdx.x;
            float4 p = g_sv4[b][n];
            p.z = g_v2[b][n];
            sS[threadIdx.x] = p;
        }
        __syncthreads();

        #pragma unroll
        for (int kf = 0; kf < 4; kf++) {
            const int kb = kf * 16 + 2 * tig;
            float4 qa = sS[kb];
            float4 qb = sS[kb + 1];
            float4 qc = sS[kb + 8];
            float4 qd = sS[kb + 9];

            unsigned a0 = pack2(attn_val(plo.x, plo.y, plo.z, qa), attn_val(plo.x, plo.y, plo.z, qb));
            unsigned a1 = pack2(attn_val(phi.x, phi.y, phi.z, qa), attn_val(phi.x, phi.y, phi.z, qb));
            unsigned a2 = pack2(attn_val(plo.x, plo.y, plo.z, qc), attn_val(plo.x, plo.y, plo.z, qd));
            unsigned a3 = pack2(attn_val(phi.x, phi.y, phi.z, qc), attn_val(phi.x, phi.y, phi.z, qd));

            #pragma unroll
            for (int j = 0; j < 16; j++) {
                const __half* brow = &sB[chalf * 128 + j * 8 + gid][kf * 16 + 2 * tig];
                unsigned b0 = *reinterpret_cast<const unsigned*>(brow);
                unsigned b1 = *reinterpret_cast<const unsigned*>(brow + 8);
                mma16816(acc[j][0], acc[j][1], acc[j][2], acc[j][3],
                         a0, a1, a2, a3, b0, b1);
            }
        }
    }

    const int orlo = g_tperm[b][rlo];
    const int orhi = g_tperm[b][rhi];
    #pragma unroll
    for (int j = 0; j < 16; j++) {
        int c = chalf * 128 + j * 8 + 2 * tig;
        float2 vlo = haslo ? make_float2(acc[j][0], acc[j][1]) : make_float2(0.f, 0.f);
        float2 vhi = hashi ? make_float2(acc[j][2], acc[j][3]) : make_float2(0.f, 0.f);
        *reinterpret_cast<float2*>(&out[((b * Mm + orlo) * Cc) + c]) = vlo;
        *reinterpret_cast<float2*>(&out[((b * Mm + orhi) * Cc) + c]) = vhi;
    }
}

// ------------------------------- launch ---------------------------------------
extern "C" void kernel_launch(void* const* d_in, const int* in_sizes, int n_in,
                              void* d_out, int out_size) {
    const float* feats = (const float*)d_in[0];
    const float* slocs = (const float*)d_in[1];
    const float* tlocs = (const float*)d_in[2];
    const void*  smask = d_in[3];
    const void*  tmask = d_in[4];
    float* out = (float*)d_out;

    prep_kernel<<<(Bz * Nn + 255) / 256, 256>>>(slocs, tlocs, smask, tmask);   // 1
    sort_scatter_kernel<<<dim3(2, Bz), 1024>>>();                               // 2
    csr_build<<<dim3(4096 / 8, Bz, 2), 256>>>();                                // 3

    for (int it = 0; it < 3; it++) {
        lse_kernel<0><<<dim3(4096 / 8, Bz), 256>>>(it);                         // 4 <- profiled
        lse_kernel<1><<<dim3(4096 / 8, Bz), 256>>>(it);
    }

    feats_transpose<<<dim3(Nn / 32, Cc / 32, Bz), dim3(32, 8)>>>(feats);
    gemm_kernel<<<dim3(Mm / GBM, Bz), 256>>>(out);
}

// round 13
// speedup vs baseline: 1.3830x; 1.3830x over previous
#include <cuda_runtime.h>
#include <cuda_fp16.h>
#include <stdint.h>

#define Bz 4
#define Nn 4096
#define Mm 4096
#define Cc 256
#define RSTRIDE 768

#define BIG2 1.0e9f
// (-1/(EPSILON+1e-8)) * log2(e)
__device__ __constant__ float c_NEG_INV2 = (float)(-1.0 / 0.01000001 * 1.4426950408889634);

// ---------------- persistent device scratch (no runtime alloc) ----------------
__device__ __align__(16) float2 g_sl0[Bz][Nn];
__device__ __align__(16) float2 g_tl0[Bz][Mm];
__device__ unsigned char g_sok0[Bz][Nn];
__device__ int g_tkey[Bz][Mm];
__device__ int g_skey[Bz][Nn];
__device__ int g_tperm[Bz][Mm];
__device__ int g_sperm[Bz][Nn];

// SORTED coords
__device__ __align__(16) float4 g_sv4[Bz][Nn];
__device__ __align__(16) float4 g_tu4[Bz][Mm];
__device__ unsigned char g_sok[Bz][Nn];
__device__ unsigned char g_has[Bz][Mm];
__device__ __align__(16) float4 g_sbb[Bz][Nn / 32];
__device__ __align__(16) float4 g_tbb[Bz][Mm / 32];

// duals (log2 domain) + their exponentials
__device__ float g_u2[Bz][Mm];
__device__ float g_v2[Bz][Nn];
__device__ __align__(16) float g_eu[Bz][Mm];
__device__ __align__(16) float g_ev[Bz][Nn];
__device__ int g_cnt0u[3 * Bz];
__device__ int g_cnt0v[3 * Bz];

// padded CSR, SoA: col (u16) + K = exp2(lk2) (f32)
__device__ __align__(16) unsigned short g_colT[Bz][Mm * RSTRIDE];
__device__ __align__(16) unsigned short g_colS[Bz][Nn * RSTRIDE];
__device__ __align__(16) float g_valT[Bz][Mm * RSTRIDE];
__device__ __align__(16) float g_valS[Bz][Nn * RSTRIDE];
__device__ int g_nnzT[Bz][Mm];
__device__ int g_nnzS[Bz][Nn];

__device__ __align__(16) __half g_fT[Bz][Cc][Nn];

// ---------------- mask dtype auto-detect ------------------------------------
__device__ __forceinline__ int detect_fmt(const unsigned* w) {
    bool sawF = false, sawU = false;
    for (int i = 0; i < 64; i++) {
        unsigned v = w[i];
        if (v == 0x3F800000u) sawF = true;
        else if (v > 1u) {
            unsigned b0 = v & 255u, b1 = (v >> 8) & 255u, b2 = (v >> 16) & 255u, b3 = v >> 24;
            if (b0 <= 1u && b1 <= 1u && b2 <= 1u && b3 <= 1u) sawU = true;
            else sawF = true;
        }
    }
    if (sawF) return 2;
    if (sawU) return 0;
    return 1;
}
__device__ __forceinline__ bool read_mask(const void* p, int i, int fmt) {
    if (fmt == 0) return ((const unsigned char*)p)[i] != 0;
    if (fmt == 1) return ((const int*)p)[i] != 0;
    return ((const float*)p)[i] != 0.0f;
}

__device__ __forceinline__ unsigned spread4(unsigned x) {
    x &= 15u; x = (x | (x << 2)) & 0x33u; x = (x | (x << 1)) & 0x55u; return x;
}
__device__ __forceinline__ int morton_key(float x, float y) {
    int cx = (int)(x * 16.0f); cx = cx < 0 ? 0 : (cx > 15 ? 15 : cx);
    int cy = (int)(y * 16.0f); cy = cy < 0 ? 0 : (cy > 15 ? 15 : cy);
    return (int)(spread4((unsigned)cx) | (spread4((unsigned)cy) << 1));
}

// ---------------- prep -------------------------------------------------------
__global__ void prep_kernel(const float* __restrict__ slocs,
                            const float* __restrict__ tlocs,
                            const void* __restrict__ smask,
                            const void* __restrict__ tmask) {
    __shared__ int sf[2];
    if (threadIdx.x == 0) {
        sf[0] = detect_fmt((const unsigned*)smask);
        sf[1] = detect_fmt((const unsigned*)tmask);
    }
    __syncthreads();
    int i = blockIdx.x * blockDim.x + threadIdx.x;
    if (blockIdx.x == 0 && threadIdx.x < 3 * Bz) {
        g_cnt0u[threadIdx.x] = 0;
        g_cnt0v[threadIdx.x] = 0;
    }
    if (i >= Bz * Nn) return;
    int b = i / Nn, n = i % Nn;

    bool sok = read_mask(smask, i, sf[0]);
    float sx = slocs[2 * i], sy = slocs[2 * i + 1];
    g_sl0[b][n] = make_float2(sok ? sx : -1e18f, sy);
    g_sok0[b][n] = sok ? 1 : 0;
    g_skey[b][n] = sok ? morton_key(sx, sy) : 256;
    g_v2[b][n] = 0.0f;
    g_ev[b][n] = 1.0f;

    bool tok = read_mask(tmask, i, sf[1]);
    float tx = tlocs[2 * i], ty = tlocs[2 * i + 1];
    g_tl0[b][n] = make_float2(tok ? tx : 1e18f, ty);
    g_tkey[b][n] = tok ? morton_key(tx, ty) : 256;
}

// ---------------- fused bitonic sort + scatter + chunk bboxes -----------------
__global__ __launch_bounds__(1024) void sort_scatter_kernel() {
    __shared__ unsigned sk[4096];
    int side = blockIdx.x, b = blockIdx.y, tid = threadIdx.x;
    int lane = tid & 31;
    for (int i = tid; i < 4096; i += 1024) {
        int key = side ? g_skey[b][i] : g_tkey[b][i];
        sk[i] = ((unsigned)key << 12) | (unsigned)i;
    }
    __syncthreads();
    for (int k = 2; k <= 4096; k <<= 1) {
        for (int j = k >> 1; j >= 1; j >>= 1) {
            for (int i = tid; i < 4096; i += 1024) {
                int l = i ^ j;
                if (l > i) {
                    unsigned a = sk[i], c = sk[l];
                    bool up = ((i & k) == 0);
                    if ((a > c) == up) { sk[i] = c; sk[l] = a; }
                }
            }
            __syncthreads();
        }
    }
    for (int i = tid; i < 4096; i += 1024) {
        int idx = (int)(sk[i] & 0xFFFu);
        float2 p;
        if (side) {
            p = g_sl0[b][idx];
            g_sv4[b][i] = make_float4(p.x, p.y, 0.0f, 0.0f);
            g_sok[b][i] = g_sok0[b][idx];
            g_sperm[b][i] = idx;
        } else {
            p = g_tl0[b][idx];
            g_tu4[b][i] = make_float4(p.x, p.y, 0.0f, 0.0f);
            g_tperm[b][i] = idx;
        }
        float mnx = p.x, mxx = p.x, mny = p.y, mxy = p.y;
        #pragma unroll
        for (int off = 16; off; off >>= 1) {
            mnx = fminf(mnx, __shfl_xor_sync(0xffffffffu, mnx, off));
            mxx = fmaxf(mxx, __shfl_xor_sync(0xffffffffu, mxx, off));
            mny = fminf(mny, __shfl_xor_sync(0xffffffffu, mny, off));
            mxy = fmaxf(mxy, __shfl_xor_sync(0xffffffffu, mxy, off));
        }
        if (lane == 0) {
            int chunk = i >> 5;
            float4 bb = make_float4(mnx, mny, mxx, mxy);
            if (side) g_sbb[b][chunk] = bb; else g_tbb[b][chunk] = bb;
        }
    }
}

// ---------------- build padded CSR (cols + K f32) once -------------------------
__global__ __launch_bounds__(256) void csr_build() {
    const int b = blockIdx.y, side = blockIdx.z;
    const int warp = threadIdx.x >> 5, lane = threadIdx.x & 31;
    const int row = blockIdx.x * 8 + warp;
    const unsigned FULL = 0xffffffffu;
    const float NEG_INV2 = c_NEG_INV2;

    float4 rp = (side == 0) ? g_tu4[b][row] : g_sv4[b][row];
    const float4* opp = (side == 0) ? g_sv4[b] : g_tu4[b];
    const float4* bb  = (side == 0) ? g_sbb[b] : g_tbb[b];
    unsigned short* cseg = ((side == 0) ? g_colT[b] : g_colS[b]) + (size_t)row * RSTRIDE;
    float*          vseg = ((side == 0) ? g_valT[b] : g_valS[b]) + (size_t)row * RSTRIDE;

    int cnt = 0;
    #pragma unroll
    for (int t = 0; t < 4; t++) {
        int c = t * 32 + lane;
        float4 cb = bb[c];
        float ddx = fmaxf(fmaxf(cb.x - rp.x, rp.x - cb.z), 0.0f);
        float ddy = fmaxf(fmaxf(cb.y - rp.y, rp.y - cb.w), 0.0f);
        bool inc = (ddx * ddx + ddy * ddy < 0.0401f);
        unsigned mask = __ballot_sync(FULL, inc);
        while (mask) {
            int chunk = t * 32 + (__ffs(mask) - 1);
            mask &= mask - 1;
            int col = chunk * 32 + lane;
            float4 q = opp[col];
            float dx = __fadd_rn(rp.x, -q.x);
            float dy = __fadd_rn(rp.y, -q.y);
            float d2 = __fadd_rn(__fmul_rn(dx, dx), __fmul_rn(dy, dy));
            bool valid = (d2 < 0.04f);
            unsigned vm = __ballot_sync(FULL, valid);
            if (valid) {
                int slot = cnt + __popc(vm & ((1u << lane) - 1u));
                if (slot < RSTRIDE) {
                    cseg[slot] = (unsigned short)col;
                    vseg[slot] = exp2f(__fmul_rn(d2, NEG_INV2));
                }
            }
            cnt += __popc(vm);
        }
    }
    if (lane == 0) {
        cnt = cnt > RSTRIDE ? RSTRIDE : cnt;
        if (side == 0) { g_nnzT[b][row] = cnt; g_has[b][row] = (cnt > 0) ? 1 : 0; }
        else           { g_nnzS[b][row] = cnt; }
    }
}

// ---------------- LSE pass: FMA stream over SoA CSR (R9 form) -----------------
// grid (4096/8, Bz); block 256 = 8 warps; warp = row
template <int MODE>
__global__ __launch_bounds__(256) void lse_kernel(int iter) {
    const int b = blockIdx.y;
    const int warp = threadIdx.x >> 5, lane = threadIdx.x & 31;
    const int row = blockIdx.x * 8 + warp;
    const unsigned FULL = 0xffffffffu;

    const unsigned short* cseg = ((MODE == 0) ? g_colT[b] : g_colS[b]) + (size_t)row * RSTRIDE;
    const float*          vseg = ((MODE == 0) ? g_valT[b] : g_valS[b]) + (size_t)row * RSTRIDE;
    const float*          ed   = (MODE == 0) ? g_ev[b] : g_eu[b];
    const int cnt = (MODE == 0) ? g_nnzT[b][row] : g_nnzS[b][row];

    float s0 = 0.0f, s1 = 0.0f;
    int i = 2 * lane;
    for (; i + 1 < cnt; i += 64) {
        unsigned cc = *(const unsigned*)(cseg + i);     // 2 cols
        float2 kk = *(const float2*)(vseg + i);          // 2 Ks
        s0 = __fmaf_rn(kk.x, ed[cc & 0xFFFFu], s0);
        s1 = __fmaf_rn(kk.y, ed[cc >> 16], s1);
    }
    if (i < cnt) s0 = __fmaf_rn(vseg[i], ed[cseg[i]], s0);

    float s = s0 + s1;
    #pragma unroll
    for (int off = 16; off; off >>= 1) s += __shfl_xor_sync(FULL, s, off);

    if (lane == 0) {
        if (MODE == 0) {
            float tot = s + ((iter > 0) ? (float)g_cnt0v[(iter - 1) * Bz + b] : 0.0f);
            float u2;
            if (tot > 0.0f) u2 = -log2f(tot);
            else { u2 = BIG2; atomicAdd(&g_cnt0u[iter * Bz + b], 1); }
            g_u2[b][row] = u2;
            g_eu[b][row] = (tot > 0.0f) ? exp2f(u2) : 1.0f;
        } else {
            float tot = s + (float)g_cnt0u[iter * Bz + b];
            bool sok = g_sok[b][row] != 0;
            float v2;
            if (tot > 0.0f) v2 = -log2f(tot);
            else { v2 = BIG2; if (sok) atomicAdd(&g_cnt0v[iter * Bz + b], 1); }
            v2 = sok ? v2 : 0.0f;
            g_v2[b][row] = v2;
            g_ev[b][row] = (tot > 0.0f || !sok) ? exp2f(v2) : 1.0f;
        }
    }
}

// ---------------- feats f32 [b][orig n][c] -> fp16 [b][c][sorted n] ----------
__global__ void feats_transpose(const float* __restrict__ f) {
    __shared__ float tile[32][33];
    int b = blockIdx.z;
    int n0 = blockIdx.x * 32, c0 = blockIdx.y * 32;
    int tx = threadIdx.x, ty = threadIdx.y;
    #pragma unroll
    for (int j = 0; j < 4; j++) {
        int n = n0 + ty + j * 8;
        int on = g_sperm[b][n];
        tile[ty + j * 8][tx] = f[((b * Nn + on) * Cc) + (c0 + tx)];
    }
    __syncthreads();
    #pragma unroll
    for (int j = 0; j < 4; j++) {
        int c = c0 + ty + j * 8;
        g_fT[b][c][n0 + tx] = __float2half(tile[tx][ty + j * 8]);
    }
}

// ---------------- fused attn-recompute GEMM (c-split warps, R10 form) --------
__device__ __forceinline__ void mma16816(float& c0, float& c1, float& c2, float& c3,
                                         unsigned a0, unsigned a1, unsigned a2, unsigned a3,
                                         unsigned b0, unsigned b1) {
    asm volatile(
        "mma.sync.aligned.m16n8k16.row.col.f32.f16.f16.f32 "
        "{%0,%1,%2,%3}, {%4,%5,%6,%7}, {%8,%9}, {%0,%1,%2,%3};\n"
        : "+f"(c0), "+f"(c1), "+f"(c2), "+f"(c3)
        : "r"(a0), "r"(a1), "r"(a2), "r"(a3), "r"(b0), "r"(b1));
}

__device__ __forceinline__ float attn_val(float txx, float tyy, float uu2, float4 q) {
    float dx = __fadd_rn(txx, -q.x);
    float dy = __fadd_rn(tyy, -q.y);
    float d2 = __fadd_rn(__fmul_rn(dx, dx), __fmul_rn(dy, dy));
    if (d2 < 0.04f)
        return exp2f(__fadd_rn(__fmaf_rn(d2, c_NEG_INV2, uu2), q.z));
    return 0.0f;
}

__device__ __forceinline__ unsigned pack2(float x, float y) {
    __half2 h = __floats2half2_rn(x, y);
    return *reinterpret_cast<unsigned*>(&h);
}

#define GBM 64
#define GBC 128
#define GBK 64
#define SBSTRIDE 72

// 256 threads = 8 warps = 4 m-groups x 2 c-halves; grid (64, 2, Bz)
__global__ __launch_bounds__(256) void gemm_kernel(float* __restrict__ out) {
    const int b  = blockIdx.z;
    const int m0 = blockIdx.x * GBM;
    const int c0 = blockIdx.y * GBC;
    const int warp = threadIdx.x >> 5, lane = threadIdx.x & 31;
    const int mg = warp >> 1, chalf = warp & 1;
    const int gid = lane >> 2, tig = lane & 3;

    __shared__ __align__(16) __half sB[GBC][SBSTRIDE];
    __shared__ __align__(16) float4 sS[GBK];

    float tmnx, tmxx, tmny, tmxy;
    {
        float4 b0 = g_tbb[b][(m0 >> 5) + 0], b1 = g_tbb[b][(m0 >> 5) + 1];
        tmnx = fminf(b0.x, b1.x); tmny = fminf(b0.y, b1.y);
        tmxx = fmaxf(b0.z, b1.z); tmxy = fmaxf(b0.w, b1.w);
    }

    const int rlo = m0 + mg * 16 + gid;
    const int rhi = rlo + 8;
    float4 plo = g_tu4[b][rlo]; plo.z = g_u2[b][rlo];
    float4 phi = g_tu4[b][rhi]; phi.z = g_u2[b][rhi];
    const bool haslo = g_has[b][rlo] != 0;
    const bool hashi = g_has[b][rhi] != 0;

    float acc[8][4];
    #pragma unroll
    for (int j = 0; j < 8; j++) {
        acc[j][0] = 0.f; acc[j][1] = 0.f; acc[j][2] = 0.f; acc[j][3] = 0.f;
    }

    for (int n0 = 0; n0 < Nn; n0 += GBK) {
        {
            float4 s0 = g_sbb[b][(n0 >> 5) + 0], s1 = g_sbb[b][(n0 >> 5) + 1];
            float smnx = fminf(s0.x, s1.x), smny = fminf(s0.y, s1.y);
            float smxx = fmaxf(s0.z, s1.z), smxy = fmaxf(s0.w, s1.w);
            float ddx = fmaxf(fmaxf(smnx - tmxx, tmnx - smxx), 0.0f);
            float ddy = fmaxf(fmaxf(smny - tmxy, tmny - smxy), 0.0f);
            if (ddx * ddx + ddy * ddy >= 0.0401f) continue;
        }
        __syncthreads();
        {
            int idx = threadIdx.x;                 // 256 threads, 1024 uint4
            #pragma unroll
            for (int t = 0; t < 4; t++, idx += 256) {
                int row = idx >> 3, ch8 = idx & 7;
                const uint4* src = reinterpret_cast<const uint4*>(&g_fT[b][c0 + row][n0]) + ch8;
                *reinterpret_cast<uint4*>(&sB[row][ch8 * 8]) = *src;
            }
        }
        if (threadIdx.x < GBK) {
            int n = n0 + threadIdx.x;
            float4 p = g_sv4[b][n];
            p.z = g_v2[b][n];
            sS[threadIdx.x] = p;
        }
        __syncthreads();

        #pragma unroll
        for (int kf = 0; kf < 4; kf++) {
            const int kb = kf * 16 + 2 * tig;
            float4 qa = sS[kb];
            float4 qb = sS[kb + 1];
            float4 qc = sS[kb + 8];
            float4 qd = sS[kb + 9];

            unsigned a0 = pack2(attn_val(plo.x, plo.y, plo.z, qa), attn_val(plo.x, plo.y, plo.z, qb));
            unsigned a1 = pack2(attn_val(phi.x, phi.y, phi.z, qa), attn_val(phi.x, phi.y, phi.z, qb));
            unsigned a2 = pack2(attn_val(plo.x, plo.y, plo.z, qc), attn_val(plo.x, plo.y, plo.z, qd));
            unsigned a3 = pack2(attn_val(phi.x, phi.y, phi.z, qc), attn_val(phi.x, phi.y, phi.z, qd));

            #pragma unroll
            for (int j = 0; j < 8; j++) {
                const __half* brow = &sB[chalf * 64 + j * 8 + gid][kf * 16 + 2 * tig];
                unsigned b0 = *reinterpret_cast<const unsigned*>(brow);
                unsigned b1 = *reinterpret_cast<const unsigned*>(brow + 8);
                mma16816(acc[j][0], acc[j][1], acc[j][2], acc[j][3],
                         a0, a1, a2, a3, b0, b1);
            }
        }
    }

    const int orlo = g_tperm[b][rlo];
    const int orhi = g_tperm[b][rhi];
    #pragma unroll
    for (int j = 0; j < 8; j++) {
        int c = c0 + chalf * 64 + j * 8 + 2 * tig;
        float2 vlo = haslo ? make_float2(acc[j][0], acc[j][1]) : make_float2(0.f, 0.f);
        float2 vhi = hashi ? make_float2(acc[j][2], acc[j][3]) : make_float2(0.f, 0.f);
        *reinterpret_cast<float2*>(&out[((b * Mm + orlo) * Cc) + c]) = vlo;
        *reinterpret_cast<float2*>(&out[((b * Mm + orhi) * Cc) + c]) = vhi;
    }
}

// ------------------------------- launch ---------------------------------------
extern "C" void kernel_launch(void* const* d_in, const int* in_sizes, int n_in,
                              void* d_out, int out_size) {
    const float* feats = (const float*)d_in[0];
    const float* slocs = (const float*)d_in[1];
    const float* tlocs = (const float*)d_in[2];
    const void*  smask = d_in[3];
    const void*  tmask = d_in[4];
    float* out = (float*)d_out;

    prep_kernel<<<(Bz * Nn + 255) / 256, 256>>>(slocs, tlocs, smask, tmask);   // 1
    sort_scatter_kernel<<<dim3(2, Bz), 1024>>>();                               // 2
    csr_build<<<dim3(4096 / 8, Bz, 2), 256>>>();                                // 3

    for (int it = 0; it < 3; it++) {
        lse_kernel<0><<<dim3(4096 / 8, Bz), 256>>>(it);                         // 4 <- profiled
        lse_kernel<1><<<dim3(4096 / 8, Bz), 256>>>(it);
    }

    feats_transpose<<<dim3(Nn / 32, Cc / 32, Bz), dim3(32, 8)>>>(feats);
    gemm_kernel<<<dim3(Mm / GBM, GBC == 128 ? 2 : 1, Bz), 256>>>(out);
}

// round 14
// speedup vs baseline: 1.3859x; 1.0021x over previous
#include <cuda_runtime.h>
#include <cuda_fp16.h>
#include <stdint.h>

#define Bz 4
#define Nn 4096
#define Mm 4096
#define Cc 256
#define RSTRIDE 768

#define BIG2 1.0e9f
// (-1/(EPSILON+1e-8)) * log2(e)
__device__ __constant__ float c_NEG_INV2 = (float)(-1.0 / 0.01000001 * 1.4426950408889634);

// ---------------- persistent device scratch (no runtime alloc) ----------------
__device__ __align__(16) float2 g_sl0[Bz][Nn];
__device__ __align__(16) float2 g_tl0[Bz][Mm];
__device__ unsigned char g_sok0[Bz][Nn];
__device__ int g_tkey[Bz][Mm];
__device__ int g_skey[Bz][Nn];
__device__ int g_tperm[Bz][Mm];
__device__ int g_sperm[Bz][Nn];

// SORTED coords
__device__ __align__(16) float4 g_sv4[Bz][Nn];
__device__ __align__(16) float4 g_tu4[Bz][Mm];
__device__ unsigned char g_sok[Bz][Nn];
__device__ unsigned char g_has[Bz][Mm];
__device__ __align__(16) float4 g_sbb[Bz][Nn / 32];
__device__ __align__(16) float4 g_tbb[Bz][Mm / 32];

// duals (log2 domain) + their exponentials
__device__ float g_u2[Bz][Mm];
__device__ float g_v2[Bz][Nn];
__device__ __align__(16) float g_eu[Bz][Mm];
__device__ __align__(16) float g_ev[Bz][Nn];
__device__ int g_cnt0u[3 * Bz];
__device__ int g_cnt0v[3 * Bz];

// padded CSR, SoA: col (u16) + K = exp2(lk2) (f32)
__device__ __align__(16) unsigned short g_colT[Bz][Mm * RSTRIDE];
__device__ __align__(16) unsigned short g_colS[Bz][Nn * RSTRIDE];
__device__ __align__(16) float g_valT[Bz][Mm * RSTRIDE];
__device__ __align__(16) float g_valS[Bz][Nn * RSTRIDE];
__device__ int g_nnzT[Bz][Mm];
__device__ int g_nnzS[Bz][Nn];

__device__ __align__(16) __half g_fT[Bz][Cc][Nn];

// ---------------- mask dtype auto-detect ------------------------------------
__device__ __forceinline__ int detect_fmt(const unsigned* w) {
    bool sawF = false, sawU = false;
    for (int i = 0; i < 64; i++) {
        unsigned v = w[i];
        if (v == 0x3F800000u) sawF = true;
        else if (v > 1u) {
            unsigned b0 = v & 255u, b1 = (v >> 8) & 255u, b2 = (v >> 16) & 255u, b3 = v >> 24;
            if (b0 <= 1u && b1 <= 1u && b2 <= 1u && b3 <= 1u) sawU = true;
            else sawF = true;
        }
    }
    if (sawF) return 2;
    if (sawU) return 0;
    return 1;
}
__device__ __forceinline__ bool read_mask(const void* p, int i, int fmt) {
    if (fmt == 0) return ((const unsigned char*)p)[i] != 0;
    if (fmt == 1) return ((const int*)p)[i] != 0;
    return ((const float*)p)[i] != 0.0f;
}

__device__ __forceinline__ unsigned spread4(unsigned x) {
    x &= 15u; x = (x | (x << 2)) & 0x33u; x = (x | (x << 1)) & 0x55u; return x;
}
__device__ __forceinline__ int morton_key(float x, float y) {
    int cx = (int)(x * 16.0f); cx = cx < 0 ? 0 : (cx > 15 ? 15 : cx);
    int cy = (int)(y * 16.0f); cy = cy < 0 ? 0 : (cy > 15 ? 15 : cy);
    return (int)(spread4((unsigned)cx) | (spread4((unsigned)cy) << 1));
}

// ---------------- prep -------------------------------------------------------
__global__ void prep_kernel(const float* __restrict__ slocs,
                            const float* __restrict__ tlocs,
                            const void* __restrict__ smask,
                            const void* __restrict__ tmask) {
    __shared__ int sf[2];
    if (threadIdx.x == 0) {
        sf[0] = detect_fmt((const unsigned*)smask);
        sf[1] = detect_fmt((const unsigned*)tmask);
    }
    __syncthreads();
    int i = blockIdx.x * blockDim.x + threadIdx.x;
    if (blockIdx.x == 0 && threadIdx.x < 3 * Bz) {
        g_cnt0u[threadIdx.x] = 0;
        g_cnt0v[threadIdx.x] = 0;
    }
    if (i >= Bz * Nn) return;
    int b = i / Nn, n = i % Nn;

    bool sok = read_mask(smask, i, sf[0]);
    float sx = slocs[2 * i], sy = slocs[2 * i + 1];
    g_sl0[b][n] = make_float2(sok ? sx : -1e18f, sy);
    g_sok0[b][n] = sok ? 1 : 0;
    g_skey[b][n] = sok ? morton_key(sx, sy) : 256;
    g_v2[b][n] = 0.0f;
    g_ev[b][n] = 1.0f;

    bool tok = read_mask(tmask, i, sf[1]);
    float tx = tlocs[2 * i], ty = tlocs[2 * i + 1];
    g_tl0[b][n] = make_float2(tok ? tx : 1e18f, ty);
    g_tkey[b][n] = tok ? morton_key(tx, ty) : 256;
}

// ---------------- fused bitonic sort + scatter + chunk bboxes -----------------
__global__ __launch_bounds__(1024) void sort_scatter_kernel() {
    __shared__ unsigned sk[4096];
    int side = blockIdx.x, b = blockIdx.y, tid = threadIdx.x;
    int lane = tid & 31;
    for (int i = tid; i < 4096; i += 1024) {
        int key = side ? g_skey[b][i] : g_tkey[b][i];
        sk[i] = ((unsigned)key << 12) | (unsigned)i;
    }
    __syncthreads();
    for (int k = 2; k <= 4096; k <<= 1) {
        for (int j = k >> 1; j >= 1; j >>= 1) {
            for (int i = tid; i < 4096; i += 1024) {
                int l = i ^ j;
                if (l > i) {
                    unsigned a = sk[i], c = sk[l];
                    bool up = ((i & k) == 0);
                    if ((a > c) == up) { sk[i] = c; sk[l] = a; }
                }
            }
            __syncthreads();
        }
    }
    for (int i = tid; i < 4096; i += 1024) {
        int idx = (int)(sk[i] & 0xFFFu);
        float2 p;
        if (side) {
            p = g_sl0[b][idx];
            g_sv4[b][i] = make_float4(p.x, p.y, 0.0f, 0.0f);
            g_sok[b][i] = g_sok0[b][idx];
            g_sperm[b][i] = idx;
        } else {
            p = g_tl0[b][idx];
            g_tu4[b][i] = make_float4(p.x, p.y, 0.0f, 0.0f);
            g_tperm[b][i] = idx;
        }
        float mnx = p.x, mxx = p.x, mny = p.y, mxy = p.y;
        #pragma unroll
        for (int off = 16; off; off >>= 1) {
            mnx = fminf(mnx, __shfl_xor_sync(0xffffffffu, mnx, off));
            mxx = fmaxf(mxx, __shfl_xor_sync(0xffffffffu, mxx, off));
            mny = fminf(mny, __shfl_xor_sync(0xffffffffu, mny, off));
            mxy = fmaxf(mxy, __shfl_xor_sync(0xffffffffu, mxy, off));
        }
        if (lane == 0) {
            int chunk = i >> 5;
            float4 bb = make_float4(mnx, mny, mxx, mxy);
            if (side) g_sbb[b][chunk] = bb; else g_tbb[b][chunk] = bb;
        }
    }
}

// ---------------- build padded CSR (cols + K f32) once -------------------------
__global__ __launch_bounds__(256) void csr_build() {
    const int b = blockIdx.y, side = blockIdx.z;
    const int warp = threadIdx.x >> 5, lane = threadIdx.x & 31;
    const int row = blockIdx.x * 8 + warp;
    const unsigned FULL = 0xffffffffu;
    const float NEG_INV2 = c_NEG_INV2;

    float4 rp = (side == 0) ? g_tu4[b][row] : g_sv4[b][row];
    const float4* opp = (side == 0) ? g_sv4[b] : g_tu4[b];
    const float4* bb  = (side == 0) ? g_sbb[b] : g_tbb[b];
    unsigned short* cseg = ((side == 0) ? g_colT[b] : g_colS[b]) + (size_t)row * RSTRIDE;
    float*          vseg = ((side == 0) ? g_valT[b] : g_valS[b]) + (size_t)row * RSTRIDE;

    int cnt = 0;
    #pragma unroll
    for (int t = 0; t < 4; t++) {
        int c = t * 32 + lane;
        float4 cb = bb[c];
        float ddx = fmaxf(fmaxf(cb.x - rp.x, rp.x - cb.z), 0.0f);
        float ddy = fmaxf(fmaxf(cb.y - rp.y, rp.y - cb.w), 0.0f);
        bool inc = (ddx * ddx + ddy * ddy < 0.0401f);
        unsigned mask = __ballot_sync(FULL, inc);
        while (mask) {
            int chunk = t * 32 + (__ffs(mask) - 1);
            mask &= mask - 1;
            int col = chunk * 32 + lane;
            float4 q = opp[col];
            float dx = __fadd_rn(rp.x, -q.x);
            float dy = __fadd_rn(rp.y, -q.y);
            float d2 = __fadd_rn(__fmul_rn(dx, dx), __fmul_rn(dy, dy));
            bool valid = (d2 < 0.04f);
            unsigned vm = __ballot_sync(FULL, valid);
            if (valid) {
                int slot = cnt + __popc(vm & ((1u << lane) - 1u));
                if (slot < RSTRIDE) {
                    cseg[slot] = (unsigned short)col;
                    vseg[slot] = exp2f(__fmul_rn(d2, NEG_INV2));
                }
            }
            cnt += __popc(vm);
        }
    }
    if (lane == 0) {
        cnt = cnt > RSTRIDE ? RSTRIDE : cnt;
        if (side == 0) { g_nnzT[b][row] = cnt; g_has[b][row] = (cnt > 0) ? 1 : 0; }
        else           { g_nnzS[b][row] = cnt; }
    }
}

// ---------------- LSE pass: FMA stream over SoA CSR (R9 form) -----------------
// grid (4096/8, Bz); block 256 = 8 warps; warp = row
template <int MODE>
__global__ __launch_bounds__(256) void lse_kernel(int iter) {
    const int b = blockIdx.y;
    const int warp = threadIdx.x >> 5, lane = threadIdx.x & 31;
    const int row = blockIdx.x * 8 + warp;
    const unsigned FULL = 0xffffffffu;

    const unsigned short* cseg = ((MODE == 0) ? g_colT[b] : g_colS[b]) + (size_t)row * RSTRIDE;
    const float*          vseg = ((MODE == 0) ? g_valT[b] : g_valS[b]) + (size_t)row * RSTRIDE;
    const float*          ed   = (MODE == 0) ? g_ev[b] : g_eu[b];
    const int cnt = (MODE == 0) ? g_nnzT[b][row] : g_nnzS[b][row];

    float s0 = 0.0f, s1 = 0.0f;
    int i = 2 * lane;
    for (; i + 1 < cnt; i += 64) {
        unsigned cc = *(const unsigned*)(cseg + i);     // 2 cols
        float2 kk = *(const float2*)(vseg + i);          // 2 Ks
        s0 = __fmaf_rn(kk.x, ed[cc & 0xFFFFu], s0);
        s1 = __fmaf_rn(kk.y, ed[cc >> 16], s1);
    }
    if (i < cnt) s0 = __fmaf_rn(vseg[i], ed[cseg[i]], s0);

    float s = s0 + s1;
    #pragma unroll
    for (int off = 16; off; off >>= 1) s += __shfl_xor_sync(FULL, s, off);

    if (lane == 0) {
        if (MODE == 0) {
            float tot = s + ((iter > 0) ? (float)g_cnt0v[(iter - 1) * Bz + b] : 0.0f);
            float u2;
            if (tot > 0.0f) u2 = -log2f(tot);
            else { u2 = BIG2; atomicAdd(&g_cnt0u[iter * Bz + b], 1); }
            g_u2[b][row] = u2;
            g_eu[b][row] = (tot > 0.0f) ? exp2f(u2) : 1.0f;
        } else {
            float tot = s + (float)g_cnt0u[iter * Bz + b];
            bool sok = g_sok[b][row] != 0;
            float v2;
            if (tot > 0.0f) v2 = -log2f(tot);
            else { v2 = BIG2; if (sok) atomicAdd(&g_cnt0v[iter * Bz + b], 1); }
            v2 = sok ? v2 : 0.0f;
            g_v2[b][row] = v2;
            g_ev[b][row] = (tot > 0.0f || !sok) ? exp2f(v2) : 1.0f;
        }
    }
}

// ---------------- feats f32 [b][orig n][c] -> fp16 [b][c][sorted n] ----------
__global__ void feats_transpose(const float* __restrict__ f) {
    __shared__ float tile[32][33];
    int b = blockIdx.z;
    int n0 = blockIdx.x * 32, c0 = blockIdx.y * 32;
    int tx = threadIdx.x, ty = threadIdx.y;
    #pragma unroll
    for (int j = 0; j < 4; j++) {
        int n = n0 + ty + j * 8;
        int on = g_sperm[b][n];
        tile[ty + j * 8][tx] = f[((b * Nn + on) * Cc) + (c0 + tx)];
    }
    __syncthreads();
    #pragma unroll
    for (int j = 0; j < 4; j++) {
        int c = c0 + ty + j * 8;
        g_fT[b][c][n0 + tx] = __float2half(tile[tx][ty + j * 8]);
    }
}

// ---------------- fused attn-recompute GEMM: double-buffered pipeline --------
__device__ __forceinline__ void mma16816(float& c0, float& c1, float& c2, float& c3,
                                         unsigned a0, unsigned a1, unsigned a2, unsigned a3,
                                         unsigned b0, unsigned b1) {
    asm volatile(
        "mma.sync.aligned.m16n8k16.row.col.f32.f16.f16.f32 "
        "{%0,%1,%2,%3}, {%4,%5,%6,%7}, {%8,%9}, {%0,%1,%2,%3};\n"
        : "+f"(c0), "+f"(c1), "+f"(c2), "+f"(c3)
        : "r"(a0), "r"(a1), "r"(a2), "r"(a3), "r"(b0), "r"(b1));
}

__device__ __forceinline__ float attn_val(float txx, float tyy, float uu2, float4 q) {
    float dx = __fadd_rn(txx, -q.x);
    float dy = __fadd_rn(tyy, -q.y);
    float d2 = __fadd_rn(__fmul_rn(dx, dx), __fmul_rn(dy, dy));
    if (d2 < 0.04f)
        return exp2f(__fadd_rn(__fmaf_rn(d2, c_NEG_INV2, uu2), q.z));
    return 0.0f;
}

__device__ __forceinline__ unsigned pack2(float x, float y) {
    __half2 h = __floats2half2_rn(x, y);
    return *reinterpret_cast<unsigned*>(&h);
}

#define GBM 64
#define GBC 128
#define GBK 64
#define SBSTRIDE 72

// 256 threads = 8 warps = 4 m-groups x 2 c-halves; grid (64, 2, Bz)
__global__ __launch_bounds__(256) void gemm_kernel(float* __restrict__ out) {
    const int b  = blockIdx.z;
    const int m0 = blockIdx.x * GBM;
    const int c0 = blockIdx.y * GBC;
    const int warp = threadIdx.x >> 5, lane = threadIdx.x & 31;
    const int mg = warp >> 1, chalf = warp & 1;
    const int gid = lane >> 2, tig = lane & 3;

    __shared__ __align__(16) __half sB[2][GBC][SBSTRIDE];  // 2 x 18KB
    __shared__ __align__(16) float4 sS[2][GBK];
    __shared__ unsigned char sCL[64];
    __shared__ int sCN;

    // ---- build included-chunk list (warp 0; identical f32 bbox test) ----
    if (warp == 0) {
        float tmnx, tmxx, tmny, tmxy;
        {
            float4 b0 = g_tbb[b][(m0 >> 5) + 0], b1 = g_tbb[b][(m0 >> 5) + 1];
            tmnx = fminf(b0.x, b1.x); tmny = fminf(b0.y, b1.y);
            tmxx = fmaxf(b0.z, b1.z); tmxy = fmaxf(b0.w, b1.w);
        }
        int base = 0;
        #pragma unroll
        for (int t = 0; t < 2; t++) {
            int kc = t * 32 + lane;              // 64-pt k-chunk id
            float4 s0 = g_sbb[b][kc * 2 + 0], s1 = g_sbb[b][kc * 2 + 1];
            float smnx = fminf(s0.x, s1.x), smny = fminf(s0.y, s1.y);
            float smxx = fmaxf(s0.z, s1.z), smxy = fmaxf(s0.w, s1.w);
            float ddx = fmaxf(fmaxf(smnx - tmxx, tmnx - smxx), 0.0f);
            float ddy = fmaxf(fmaxf(smny - tmxy, tmny - smxy), 0.0f);
            bool inc = (ddx * ddx + ddy * ddy < 0.0401f);
            unsigned mask = __ballot_sync(0xffffffffu, inc);
            if (inc) sCL[base + __popc(mask & ((1u << lane) - 1u))] = (unsigned char)kc;
            base += __popc(mask);
        }
        if (lane == 0) sCN = base;
    }

    const int rlo = m0 + mg * 16 + gid;
    const int rhi = rlo + 8;
    float4 plo = g_tu4[b][rlo]; plo.z = g_u2[b][rlo];
    float4 phi = g_tu4[b][rhi]; phi.z = g_u2[b][rhi];
    const bool haslo = g_has[b][rlo] != 0;
    const bool hashi = g_has[b][rhi] != 0;

    float acc[8][4];
    #pragma unroll
    for (int j = 0; j < 8; j++) {
        acc[j][0] = 0.f; acc[j][1] = 0.f; acc[j][2] = 0.f; acc[j][3] = 0.f;
    }

    __syncthreads();           // sCL/sCN visible
    const int ccount = sCN;

    // ---- staging helper (inlined twice) ----
    #define STAGE(buf, kc) do {                                                   \
        int n0_ = (kc) * GBK;                                                     \
        int idx_ = threadIdx.x;                                                   \
        _Pragma("unroll")                                                         \
        for (int t_ = 0; t_ < 4; t_++, idx_ += 256) {                             \
            int row_ = idx_ >> 3, ch8_ = idx_ & 7;                                \
            const uint4* src_ = reinterpret_cast<const uint4*>(&g_fT[b][c0 + row_][n0_]) + ch8_; \
            *reinterpret_cast<uint4*>(&sB[buf][row_][ch8_ * 8]) = *src_;          \
        }                                                                         \
        if (threadIdx.x < GBK) {                                                  \
            int n_ = n0_ + threadIdx.x;                                           \
            float4 p_ = g_sv4[b][n_];                                             \
            p_.z = g_v2[b][n_];                                                   \
            sS[buf][threadIdx.x] = p_;                                            \
        }                                                                         \
    } while (0)

    if (ccount > 0) STAGE(0, (int)sCL[0]);

    for (int ci = 0; ci < ccount; ci++) {
        const int cur = ci & 1;
        __syncthreads();                       // staging(cur) done; prev compute done
        if (ci + 1 < ccount) STAGE(cur ^ 1, (int)sCL[ci + 1]);

        #pragma unroll
        for (int kf = 0; kf < 4; kf++) {
            const int kb = kf * 16 + 2 * tig;
            float4 qa = sS[cur][kb];
            float4 qb = sS[cur][kb + 1];
            float4 qc = sS[cur][kb + 8];
            float4 qd = sS[cur][kb + 9];

            unsigned a0 = pack2(attn_val(plo.x, plo.y, plo.z, qa), attn_val(plo.x, plo.y, plo.z, qb));
            unsigned a1 = pack2(attn_val(phi.x, phi.y, phi.z, qa), attn_val(phi.x, phi.y, phi.z, qb));
            unsigned a2 = pack2(attn_val(plo.x, plo.y, plo.z, qc), attn_val(plo.x, plo.y, plo.z, qd));
            unsigned a3 = pack2(attn_val(phi.x, phi.y, phi.z, qc), attn_val(phi.x, phi.y, phi.z, qd));

            #pragma unroll
            for (int j = 0; j < 8; j++) {
                const __half* brow = &sB[cur][chalf * 64 + j * 8 + gid][kf * 16 + 2 * tig];
                unsigned b0 = *reinterpret_cast<const unsigned*>(brow);
                unsigned b1 = *reinterpret_cast<const unsigned*>(brow + 8);
                mma16816(acc[j][0], acc[j][1], acc[j][2], acc[j][3],
                         a0, a1, a2, a3, b0, b1);
            }
        }
    }
    #undef STAGE

    const int orlo = g_tperm[b][rlo];
    const int orhi = g_tperm[b][rhi];
    #pragma unroll
    for (int j = 0; j < 8; j++) {
        int c = c0 + chalf * 64 + j * 8 + 2 * tig;
        float2 vlo = haslo ? make_float2(acc[j][0], acc[j][1]) : make_float2(0.f, 0.f);
        float2 vhi = hashi ? make_float2(acc[j][2], acc[j][3]) : make_float2(0.f, 0.f);
        *reinterpret_cast<float2*>(&out[((b * Mm + orlo) * Cc) + c]) = vlo;
        *reinterpret_cast<float2*>(&out[((b * Mm + orhi) * Cc) + c]) = vhi;
    }
}

// ------------------------------- launch ---------------------------------------
extern "C" void kernel_launch(void* const* d_in, const int* in_sizes, int n_in,
                              void* d_out, int out_size) {
    const float* feats = (const float*)d_in[0];
    const float* slocs = (const float*)d_in[1];
    const float* tlocs = (const float*)d_in[2];
    const void*  smask = d_in[3];
    const void*  tmask = d_in[4];
    float* out = (float*)d_out;

    prep_kernel<<<(Bz * Nn + 255) / 256, 256>>>(slocs, tlocs, smask, tmask);   // 1
    sort_scatter_kernel<<<dim3(2, Bz), 1024>>>();                               // 2
    csr_build<<<dim3(4096 / 8, Bz, 2), 256>>>();                                // 3

    for (int it = 0; it < 3; it++) {
        lse_kernel<0><<<dim3(4096 / 8, Bz), 256>>>(it);                         // 4 <- profiled
        lse_kernel<1><<<dim3(4096 / 8, Bz), 256>>>(it);
    }

    feats_transpose<<<dim3(Nn / 32, Cc / 32, Bz), dim3(32, 8)>>>(feats);
    gemm_kernel<<<dim3(Mm / GBM, 2, Bz), 256>>>(out);
}

// round 15
// speedup vs baseline: 1.4307x; 1.0324x over previous
#include <cuda_runtime.h>
#include <cuda_fp16.h>
#include <stdint.h>

#define Bz 4
#define Nn 4096
#define Mm 4096
#define Cc 256
#define RSTRIDE 768

#define BIG2 1.0e9f
// (-1/(EPSILON+1e-8)) * log2(e)
__device__ __constant__ float c_NEG_INV2 = (float)(-1.0 / 0.01000001 * 1.4426950408889634);

// ---------------- persistent device scratch (no runtime alloc) ----------------
__device__ __align__(16) float2 g_sl0[Bz][Nn];
__device__ __align__(16) float2 g_tl0[Bz][Mm];
__device__ unsigned char g_sok0[Bz][Nn];
__device__ int g_tkey[Bz][Mm];
__device__ int g_skey[Bz][Nn];
__device__ int g_tperm[Bz][Mm];
__device__ int g_sperm[Bz][Nn];

// SORTED coords
__device__ __align__(16) float4 g_sv4[Bz][Nn];
__device__ __align__(16) float4 g_tu4[Bz][Mm];
__device__ unsigned char g_sok[Bz][Nn];
__device__ unsigned char g_has[Bz][Mm];
__device__ __align__(16) float4 g_sbb[Bz][Nn / 32];
__device__ __align__(16) float4 g_tbb[Bz][Mm / 32];

// duals (log2 domain) + their exponentials
__device__ float g_u2[Bz][Mm];
__device__ float g_v2[Bz][Nn];
__device__ __align__(16) float g_eu[Bz][Mm];
__device__ __align__(16) float g_ev[Bz][Nn];
__device__ int g_cnt0u[3 * Bz];
__device__ int g_cnt0v[3 * Bz];

// padded CSR, SoA: col (u16) + K = exp2(lk2) (f32)
__device__ __align__(16) unsigned short g_colT[Bz][Mm * RSTRIDE];
__device__ __align__(16) unsigned short g_colS[Bz][Nn * RSTRIDE];
__device__ __align__(16) float g_valT[Bz][Mm * RSTRIDE];
__device__ __align__(16) float g_valS[Bz][Nn * RSTRIDE];
__device__ int g_nnzT[Bz][Mm];
__device__ int g_nnzS[Bz][Nn];

__device__ __align__(16) __half g_fT[Bz][Cc][Nn];

// ---------------- mask dtype auto-detect ------------------------------------
__device__ __forceinline__ int detect_fmt(const unsigned* w) {
    bool sawF = false, sawU = false;
    for (int i = 0; i < 64; i++) {
        unsigned v = w[i];
        if (v == 0x3F800000u) sawF = true;
        else if (v > 1u) {
            unsigned b0 = v & 255u, b1 = (v >> 8) & 255u, b2 = (v >> 16) & 255u, b3 = v >> 24;
            if (b0 <= 1u && b1 <= 1u && b2 <= 1u && b3 <= 1u) sawU = true;
            else sawF = true;
        }
    }
    if (sawF) return 2;
    if (sawU) return 0;
    return 1;
}
__device__ __forceinline__ bool read_mask(const void* p, int i, int fmt) {
    if (fmt == 0) return ((const unsigned char*)p)[i] != 0;
    if (fmt == 1) return ((const int*)p)[i] != 0;
    return ((const float*)p)[i] != 0.0f;
}

__device__ __forceinline__ unsigned spread4(unsigned x) {
    x &= 15u; x = (x | (x << 2)) & 0x33u; x = (x | (x << 1)) & 0x55u; return x;
}
__device__ __forceinline__ int morton_key(float x, float y) {
    int cx = (int)(x * 16.0f); cx = cx < 0 ? 0 : (cx > 15 ? 15 : cx);
    int cy = (int)(y * 16.0f); cy = cy < 0 ? 0 : (cy > 15 ? 15 : cy);
    return (int)(spread4((unsigned)cx) | (spread4((unsigned)cy) << 1));
}

// ---------------- prep -------------------------------------------------------
__global__ void prep_kernel(const float* __restrict__ slocs,
                            const float* __restrict__ tlocs,
                            const void* __restrict__ smask,
                            const void* __restrict__ tmask) {
    __shared__ int sf[2];
    if (threadIdx.x == 0) {
        sf[0] = detect_fmt((const unsigned*)smask);
        sf[1] = detect_fmt((const unsigned*)tmask);
    }
    __syncthreads();
    int i = blockIdx.x * blockDim.x + threadIdx.x;
    if (blockIdx.x == 0 && threadIdx.x < 3 * Bz) {
        g_cnt0u[threadIdx.x] = 0;
        g_cnt0v[threadIdx.x] = 0;
    }
    if (i >= Bz * Nn) return;
    int b = i / Nn, n = i % Nn;

    bool sok = read_mask(smask, i, sf[0]);
    float sx = slocs[2 * i], sy = slocs[2 * i + 1];
    g_sl0[b][n] = make_float2(sok ? sx : -1e18f, sy);
    g_sok0[b][n] = sok ? 1 : 0;
    g_skey[b][n] = sok ? morton_key(sx, sy) : 256;
    g_v2[b][n] = 0.0f;
    g_ev[b][n] = 1.0f;

    bool tok = read_mask(tmask, i, sf[1]);
    float tx = tlocs[2 * i], ty = tlocs[2 * i + 1];
    g_tl0[b][n] = make_float2(tok ? tx : 1e18f, ty);
    g_tkey[b][n] = tok ? morton_key(tx, ty) : 256;
}

// ---------------- stable counting sort + scatter + chunk bboxes ---------------
// grid (2, Bz); block 256 = 8 warps; warp w owns elements [w*512, w*512+512)
__global__ __launch_bounds__(256) void sort_scatter_kernel() {
    __shared__ int hist[8][257];             // 8.2KB: per-warp per-cell counts -> warp bases
    __shared__ int cellbase[258];
    __shared__ unsigned short ranks[4096];
    const int side = blockIdx.x, b = blockIdx.y, tid = threadIdx.x;
    const int warp = tid >> 5, lane = tid & 31;
    const unsigned FULL = 0xffffffffu;

    for (int i = tid; i < 8 * 257; i += 256) (&hist[0][0])[i] = 0;
    __syncthreads();

    // phase 1: stable per-warp ranks (rounds in index order; within round by lane)
    #pragma unroll
    for (int r = 0; r < 16; r++) {
        int i = warp * 512 + r * 32 + lane;
        int cell = side ? g_skey[b][i] : g_tkey[b][i];
        unsigned peers = __match_any_sync(FULL, cell);
        int leader = __ffs(peers) - 1;
        int rankin = __popc(peers & ((1u << lane) - 1u));
        int old = 0;
        if (lane == leader) old = atomicAdd(&hist[warp][cell], __popc(peers));
        old = __shfl_sync(FULL, old, leader);
        ranks[i] = (unsigned short)(old + rankin);
    }
    __syncthreads();

    // phase 2: per-cell prefix over warps (hist becomes warp base), cell totals
    for (int c = tid; c < 257; c += 256) {
        int run = 0;
        #pragma unroll
        for (int w = 0; w < 8; w++) {
            int t = hist[w][c];
            hist[w][c] = run;
            run += t;
        }
        cellbase[c + 1] = run;
    }
    __syncthreads();
    if (tid == 0) {
        cellbase[0] = 0;
        for (int c = 1; c <= 257; c++) cellbase[c] += cellbase[c - 1];
    }
    __syncthreads();

    // phase 3: scatter to sorted order
    #pragma unroll
    for (int r = 0; r < 16; r++) {
        int i = warp * 512 + r * 32 + lane;
        int cell = side ? g_skey[b][i] : g_tkey[b][i];
        int pos = cellbase[cell] + hist[warp][cell] + (int)ranks[i];
        if (side) {
            float2 p = g_sl0[b][i];
            g_sv4[b][pos] = make_float4(p.x, p.y, 0.0f, 0.0f);
            g_sok[b][pos] = g_sok0[b][i];
            g_sperm[b][pos] = i;
        } else {
            float2 p = g_tl0[b][i];
            g_tu4[b][pos] = make_float4(p.x, p.y, 0.0f, 0.0f);
            g_tperm[b][pos] = i;
        }
    }
    __syncthreads();   // block-wide visibility of the gmem scatter

    // phase 4: 32-pt chunk bboxes over sorted coords
    for (int i = tid; i < 4096; i += 256) {
        float4 p4 = side ? g_sv4[b][i] : g_tu4[b][i];
        float mnx = p4.x, mxx = p4.x, mny = p4.y, mxy = p4.y;
        #pragma unroll
        for (int off = 16; off; off >>= 1) {
            mnx = fminf(mnx, __shfl_xor_sync(FULL, mnx, off));
            mxx = fmaxf(mxx, __shfl_xor_sync(FULL, mxx, off));
            mny = fminf(mny, __shfl_xor_sync(FULL, mny, off));
            mxy = fmaxf(mxy, __shfl_xor_sync(FULL, mxy, off));
        }
        if (lane == 0) {
            int chunk = i >> 5;
            float4 bb = make_float4(mnx, mny, mxx, mxy);
            if (side) g_sbb[b][chunk] = bb; else g_tbb[b][chunk] = bb;
        }
    }
}

// ---------------- build padded CSR (cols + K f32) once -------------------------
__global__ __launch_bounds__(256) void csr_build() {
    const int b = blockIdx.y, side = blockIdx.z;
    const int warp = threadIdx.x >> 5, lane = threadIdx.x & 31;
    const int row = blockIdx.x * 8 + warp;
    const unsigned FULL = 0xffffffffu;
    const float NEG_INV2 = c_NEG_INV2;

    float4 rp = (side == 0) ? g_tu4[b][row] : g_sv4[b][row];
    const float4* opp = (side == 0) ? g_sv4[b] : g_tu4[b];
    const float4* bb  = (side == 0) ? g_sbb[b] : g_tbb[b];
    unsigned short* cseg = ((side == 0) ? g_colT[b] : g_colS[b]) + (size_t)row * RSTRIDE;
    float*          vseg = ((side == 0) ? g_valT[b] : g_valS[b]) + (size_t)row * RSTRIDE;

    int cnt = 0;
    #pragma unroll
    for (int t = 0; t < 4; t++) {
        int c = t * 32 + lane;
        float4 cb = bb[c];
        float ddx = fmaxf(fmaxf(cb.x - rp.x, rp.x - cb.z), 0.0f);
        float ddy = fmaxf(fmaxf(cb.y - rp.y, rp.y - cb.w), 0.0f);
        bool inc = (ddx * ddx + ddy * ddy < 0.0401f);
        unsigned mask = __ballot_sync(FULL, inc);
        while (mask) {
            int chunk = t * 32 + (__ffs(mask) - 1);
            mask &= mask - 1;
            int col = chunk * 32 + lane;
            float4 q = opp[col];
            float dx = __fadd_rn(rp.x, -q.x);
            float dy = __fadd_rn(rp.y, -q.y);
            float d2 = __fadd_rn(__fmul_rn(dx, dx), __fmul_rn(dy, dy));
            bool valid = (d2 < 0.04f);
            unsigned vm = __ballot_sync(FULL, valid);
            if (valid) {
                int slot = cnt + __popc(vm & ((1u << lane) - 1u));
                if (slot < RSTRIDE) {
                    cseg[slot] = (unsigned short)col;
                    vseg[slot] = exp2f(__fmul_rn(d2, NEG_INV2));
                }
            }
            cnt += __popc(vm);
        }
    }
    if (lane == 0) {
        cnt = cnt > RSTRIDE ? RSTRIDE : cnt;
        if (side == 0) { g_nnzT[b][row] = cnt; g_has[b][row] = (cnt > 0) ? 1 : 0; }
        else           { g_nnzS[b][row] = cnt; }
    }
}

// ---------------- LSE pass: FMA stream over SoA CSR (R9 form) -----------------
// grid (4096/8, Bz); block 256 = 8 warps; warp = row
template <int MODE>
__global__ __launch_bounds__(256) void lse_kernel(int iter) {
    const int b = blockIdx.y;
    const int warp = threadIdx.x >> 5, lane = threadIdx.x & 31;
    const int row = blockIdx.x * 8 + warp;
    const unsigned FULL = 0xffffffffu;

    const unsigned short* cseg = ((MODE == 0) ? g_colT[b] : g_colS[b]) + (size_t)row * RSTRIDE;
    const float*          vseg = ((MODE == 0) ? g_valT[b] : g_valS[b]) + (size_t)row * RSTRIDE;
    const float*          ed   = (MODE == 0) ? g_ev[b] : g_eu[b];
    const int cnt = (MODE == 0) ? g_nnzT[b][row] : g_nnzS[b][row];

    float s0 = 0.0f, s1 = 0.0f;
    int i = 2 * lane;
    for (; i + 1 < cnt; i += 64) {
        unsigned cc = *(const unsigned*)(cseg + i);     // 2 cols
        float2 kk = *(const float2*)(vseg + i);          // 2 Ks
        s0 = __fmaf_rn(kk.x, ed[cc & 0xFFFFu], s0);
        s1 = __fmaf_rn(kk.y, ed[cc >> 16], s1);
    }
    if (i < cnt) s0 = __fmaf_rn(vseg[i], ed[cseg[i]], s0);

    float s = s0 + s1;
    #pragma unroll
    for (int off = 16; off; off >>= 1) s += __shfl_xor_sync(FULL, s, off);

    if (lane == 0) {
        if (MODE == 0) {
            float tot = s + ((iter > 0) ? (float)g_cnt0v[(iter - 1) * Bz + b] : 0.0f);
            float u2;
            if (tot > 0.0f) u2 = -log2f(tot);
            else { u2 = BIG2; atomicAdd(&g_cnt0u[iter * Bz + b], 1); }
            g_u2[b][row] = u2;
            g_eu[b][row] = (tot > 0.0f) ? exp2f(u2) : 1.0f;
        } else {
            float tot = s + (float)g_cnt0u[iter * Bz + b];
            bool sok = g_sok[b][row] != 0;
            float v2;
            if (tot > 0.0f) v2 = -log2f(tot);
            else { v2 = BIG2; if (sok) atomicAdd(&g_cnt0v[iter * Bz + b], 1); }
            v2 = sok ? v2 : 0.0f;
            g_v2[b][row] = v2;
            g_ev[b][row] = (tot > 0.0f || !sok) ? exp2f(v2) : 1.0f;
        }
    }
}

// ---------------- feats f32 [b][orig n][c] -> fp16 [b][c][sorted n] ----------
__global__ void feats_transpose(const float* __restrict__ f) {
    __shared__ float tile[32][33];
    int b = blockIdx.z;
    int n0 = blockIdx.x * 32, c0 = blockIdx.y * 32;
    int tx = threadIdx.x, ty = threadIdx.y;
    #pragma unroll
    for (int j = 0; j < 4; j++) {
        int n = n0 + ty + j * 8;
        int on = g_sperm[b][n];
        tile[ty + j * 8][tx] = f[((b * Nn + on) * Cc) + (c0 + tx)];
    }
    __syncthreads();
    #pragma unroll
    for (int j = 0; j < 4; j++) {
        int c = c0 + ty + j * 8;
        g_fT[b][c][n0 + tx] = __float2half(tile[tx][ty + j * 8]);
    }
}

// ---------------- fused attn-recompute GEMM: double-buffered pipeline --------
__device__ __forceinline__ void mma16816(float& c0, float& c1, float& c2, float& c3,
                                         unsigned a0, unsigned a1, unsigned a2, unsigned a3,
                                         unsigned b0, unsigned b1) {
    asm volatile(
        "mma.sync.aligned.m16n8k16.row.col.f32.f16.f16.f32 "
        "{%0,%1,%2,%3}, {%4,%5,%6,%7}, {%8,%9}, {%0,%1,%2,%3};\n"
        : "+f"(c0), "+f"(c1), "+f"(c2), "+f"(c3)
        : "r"(a0), "r"(a1), "r"(a2), "r"(a3), "r"(b0), "r"(b1));
}

__device__ __forceinline__ float attn_val(float txx, float tyy, float uu2, float4 q) {
    float dx = __fadd_rn(txx, -q.x);
    float dy = __fadd_rn(tyy, -q.y);
    float d2 = __fadd_rn(__fmul_rn(dx, dx), __fmul_rn(dy, dy));
    if (d2 < 0.04f)
        return exp2f(__fadd_rn(__fmaf_rn(d2, c_NEG_INV2, uu2), q.z));
    return 0.0f;
}

__device__ __forceinline__ unsigned pack2(float x, float y) {
    __half2 h = __floats2half2_rn(x, y);
    return *reinterpret_cast<unsigned*>(&h);
}

#define GBM 64
#define GBC 128
#define GBK 64
#define SBSTRIDE 72

// 256 threads = 8 warps = 4 m-groups x 2 c-halves; grid (64, 2, Bz)
__global__ __launch_bounds__(256) void gemm_kernel(float* __restrict__ out) {
    const int b  = blockIdx.z;
    const int m0 = blockIdx.x * GBM;
    const int c0 = blockIdx.y * GBC;
    const int warp = threadIdx.x >> 5, lane = threadIdx.x & 31;
    const int mg = warp >> 1, chalf = warp & 1;
    const int gid = lane >> 2, tig = lane & 3;

    __shared__ __align__(16) __half sB[2][GBC][SBSTRIDE];
    __shared__ __align__(16) float4 sS[2][GBK];
    __shared__ unsigned char sCL[64];
    __shared__ int sCN;

    if (warp == 0) {
        float tmnx, tmxx, tmny, tmxy;
        {
            float4 b0 = g_tbb[b][(m0 >> 5) + 0], b1 = g_tbb[b][(m0 >> 5) + 1];
            tmnx = fminf(b0.x, b1.x); tmny = fminf(b0.y, b1.y);
            tmxx = fmaxf(b0.z, b1.z); tmxy = fmaxf(b0.w, b1.w);
        }
        int base = 0;
        #pragma unroll
        for (int t = 0; t < 2; t++) {
            int kc = t * 32 + lane;
            float4 s0 = g_sbb[b][kc * 2 + 0], s1 = g_sbb[b][kc * 2 + 1];
            float smnx = fminf(s0.x, s1.x), smny = fminf(s0.y, s1.y);
            float smxx = fmaxf(s0.z, s1.z), smxy = fmaxf(s0.w, s1.w);
            float ddx = fmaxf(fmaxf(smnx - tmxx, tmnx - smxx), 0.0f);
            float ddy = fmaxf(fmaxf(smny - tmxy, tmny - smxy), 0.0f);
            bool inc = (ddx * ddx + ddy * ddy < 0.0401f);
            unsigned mask = __ballot_sync(0xffffffffu, inc);
            if (inc) sCL[base + __popc(mask & ((1u << lane) - 1u))] = (unsigned char)kc;
            base += __popc(mask);
        }
        if (lane == 0) sCN = base;
    }

    const int rlo = m0 + mg * 16 + gid;
    const int rhi = rlo + 8;
    float4 plo = g_tu4[b][rlo]; plo.z = g_u2[b][rlo];
    float4 phi = g_tu4[b][rhi]; phi.z = g_u2[b][rhi];
    const bool haslo = g_has[b][rlo] != 0;
    const bool hashi = g_has[b][rhi] != 0;

    float acc[8][4];
    #pragma unroll
    for (int j = 0; j < 8; j++) {
        acc[j][0] = 0.f; acc[j][1] = 0.f; acc[j][2] = 0.f; acc[j][3] = 0.f;
    }

    __syncthreads();
    const int ccount = sCN;

    #define STAGE(buf, kc) do {                                                   \
        int n0_ = (kc) * GBK;                                                     \
        int idx_ = threadIdx.x;                                                   \
        _Pragma("unroll")                                                         \
        for (int t_ = 0; t_ < 4; t_++, idx_ += 256) {                             \
            int row_ = idx_ >> 3, ch8_ = idx_ & 7;                                \
            const uint4* src_ = reinterpret_cast<const uint4*>(&g_fT[b][c0 + row_][n0_]) + ch8_; \
            *reinterpret_cast<uint4*>(&sB[buf][row_][ch8_ * 8]) = *src_;          \
        }                                                                         \
        if (threadIdx.x < GBK) {                                                  \
            int n_ = n0_ + threadIdx.x;                                           \
            float4 p_ = g_sv4[b][n_];                                             \
            p_.z = g_v2[b][n_];                                                   \
            sS[buf][threadIdx.x] = p_;                                            \
        }                                                                         \
    } while (0)

    if (ccount > 0) STAGE(0, (int)sCL[0]);

    for (int ci = 0; ci < ccount; ci++) {
        const int cur = ci & 1;
        __syncthreads();
        if (ci + 1 < ccount) STAGE(cur ^ 1, (int)sCL[ci + 1]);

        #pragma unroll
        for (int kf = 0; kf < 4; kf++) {
            const int kb = kf * 16 + 2 * tig;
            float4 qa = sS[cur][kb];
            float4 qb = sS[cur][kb + 1];
            float4 qc = sS[cur][kb + 8];
            float4 qd = sS[cur][kb + 9];

            unsigned a0 = pack2(attn_val(plo.x, plo.y, plo.z, qa), attn_val(plo.x, plo.y, plo.z, qb));
            unsigned a1 = pack2(attn_val(phi.x, phi.y, phi.z, qa), attn_val(phi.x, phi.y, phi.z, qb));
            unsigned a2 = pack2(attn_val(plo.x, plo.y, plo.z, qc), attn_val(plo.x, plo.y, plo.z, qd));
            unsigned a3 = pack2(attn_val(phi.x, phi.y, phi.z, qc), attn_val(phi.x, phi.y, phi.z, qd));

            #pragma unroll
            for (int j = 0; j < 8; j++) {
                const __half* brow = &sB[cur][chalf * 64 + j * 8 + gid][kf * 16 + 2 * tig];
                unsigned b0 = *reinterpret_cast<const unsigned*>(brow);
                unsigned b1 = *reinterpret_cast<const unsigned*>(brow + 8);
                mma16816(acc[j][0], acc[j][1], acc[j][2], acc[j][3],
                         a0, a1, a2, a3, b0, b1);
            }
        }
    }
    #undef STAGE

    const int orlo = g_tperm[b][rlo];
    const int orhi = g_tperm[b][rhi];
    #pragma unroll
    for (int j = 0; j < 8; j++) {
        int c = c0 + chalf * 64 + j * 8 + 2 * tig;
        float2 vlo = haslo ? make_float2(acc[j][0], acc[j][1]) : make_float2(0.f, 0.f);
        float2 vhi = hashi ? make_float2(acc[j][2], acc[j][3]) : make_float2(0.f, 0.f);
        *reinterpret_cast<float2*>(&out[((b * Mm + orlo) * Cc) + c]) = vlo;
        *reinterpret_cast<float2*>(&out[((b * Mm + orhi) * Cc) + c]) = vhi;
    }
}

// ------------------------------- launch ---------------------------------------
extern "C" void kernel_launch(void* const* d_in, const int* in_sizes, int n_in,
                              void* d_out, int out_size) {
    const float* feats = (const float*)d_in[0];
    const float* slocs = (const float*)d_in[1];
    const float* tlocs = (const float*)d_in[2];
    const void*  smask = d_in[3];
    const void*  tmask = d_in[4];
    float* out = (float*)d_out;

    prep_kernel<<<(Bz * Nn + 255) / 256, 256>>>(slocs, tlocs, smask, tmask);   // 1
    sort_scatter_kernel<<<dim3(2, Bz), 256>>>();                                // 2
    feats_transpose<<<dim3(Nn / 32, Cc / 32, Bz), dim3(32, 8)>>>(feats);        // 3
    csr_build<<<dim3(4096 / 8, Bz, 2), 256>>>();                                // 4 <- profiled

    for (int it = 0; it < 3; it++) {
        lse_kernel<0><<<dim3(4096 / 8, Bz), 256>>>(it);
        lse_kernel<1><<<dim3(4096 / 8, Bz), 256>>>(it);
    }

    gemm_kernel<<<dim3(Mm / GBM, 2, Bz), 256>>>(out);
}

// round 16
// speedup vs baseline: 1.6013x; 1.1192x over previous
#include <cuda_runtime.h>
#include <cuda_fp16.h>
#include <stdint.h>

#define Bz 4
#define Nn 4096
#define Mm 4096
#define Cc 256
#define RSTRIDE 768

#define BIG2 1.0e9f
// (-1/(EPSILON+1e-8)) * log2(e)
__device__ __constant__ float c_NEG_INV2 = (float)(-1.0 / 0.01000001 * 1.4426950408889634);

// ---------------- persistent device scratch (no runtime alloc) ----------------
__device__ __align__(16) float2 g_sl0[Bz][Nn];
__device__ __align__(16) float2 g_tl0[Bz][Mm];
__device__ unsigned char g_sok0[Bz][Nn];
__device__ int g_tkey[Bz][Mm];
__device__ int g_skey[Bz][Nn];
__device__ int g_tperm[Bz][Mm];
__device__ int g_sperm[Bz][Nn];

// SORTED coords
__device__ __align__(16) float4 g_sv4[Bz][Nn];
__device__ __align__(16) float4 g_tu4[Bz][Mm];
__device__ unsigned char g_sok[Bz][Nn];
__device__ unsigned char g_has[Bz][Mm];
__device__ __align__(16) float4 g_sbb[Bz][Nn / 32];
__device__ __align__(16) float4 g_tbb[Bz][Mm / 32];

// duals (log2 domain) + their exponentials
__device__ float g_u2[Bz][Mm];
__device__ float g_v2[Bz][Nn];
__device__ __align__(16) float g_eu[Bz][Mm];
__device__ __align__(16) float g_ev[Bz][Nn];
__device__ int g_cnt0u[3 * Bz];
__device__ int g_cnt0v[3 * Bz];

// padded CSR, SoA: col (u16) + K = exp2(lk2) (f32)
__device__ __align__(16) unsigned short g_colT[Bz][Mm * RSTRIDE];
__device__ __align__(16) unsigned short g_colS[Bz][Nn * RSTRIDE];
__device__ __align__(16) float g_valT[Bz][Mm * RSTRIDE];
__device__ __align__(16) float g_valS[Bz][Nn * RSTRIDE];
__device__ int g_nnzT[Bz][Mm];
__device__ int g_nnzS[Bz][Nn];

__device__ __align__(16) __half g_fT[Bz][Cc][Nn];

// ---------------- mask dtype auto-detect ------------------------------------
__device__ __forceinline__ int detect_fmt(const unsigned* w) {
    bool sawF = false, sawU = false;
    for (int i = 0; i < 64; i++) {
        unsigned v = w[i];
        if (v == 0x3F800000u) sawF = true;
        else if (v > 1u) {
            unsigned b0 = v & 255u, b1 = (v >> 8) & 255u, b2 = (v >> 16) & 255u, b3 = v >> 24;
            if (b0 <= 1u && b1 <= 1u && b2 <= 1u && b3 <= 1u) sawU = true;
            else sawF = true;
        }
    }
    if (sawF) return 2;
    if (sawU) return 0;
    return 1;
}
__device__ __forceinline__ bool read_mask(const void* p, int i, int fmt) {
    if (fmt == 0) return ((const unsigned char*)p)[i] != 0;
    if (fmt == 1) return ((const int*)p)[i] != 0;
    return ((const float*)p)[i] != 0.0f;
}

__device__ __forceinline__ unsigned spread4(unsigned x) {
    x &= 15u; x = (x | (x << 2)) & 0x33u; x = (x | (x << 1)) & 0x55u; return x;
}
__device__ __forceinline__ int morton_key(float x, float y) {
    int cx = (int)(x * 16.0f); cx = cx < 0 ? 0 : (cx > 15 ? 15 : cx);
    int cy = (int)(y * 16.0f); cy = cy < 0 ? 0 : (cy > 15 ? 15 : cy);
    return (int)(spread4((unsigned)cx) | (spread4((unsigned)cy) << 1));
}

// ---------------- prep -------------------------------------------------------
__global__ void prep_kernel(const float* __restrict__ slocs,
                            const float* __restrict__ tlocs,
                            const void* __restrict__ smask,
                            const void* __restrict__ tmask) {
    __shared__ int sf[2];
    if (threadIdx.x == 0) {
        sf[0] = detect_fmt((const unsigned*)smask);
        sf[1] = detect_fmt((const unsigned*)tmask);
    }
    __syncthreads();
    int i = blockIdx.x * blockDim.x + threadIdx.x;
    if (blockIdx.x == 0 && threadIdx.x < 3 * Bz) {
        g_cnt0u[threadIdx.x] = 0;
        g_cnt0v[threadIdx.x] = 0;
    }
    if (i >= Bz * Nn) return;
    int b = i / Nn, n = i % Nn;

    bool sok = read_mask(smask, i, sf[0]);
    float sx = slocs[2 * i], sy = slocs[2 * i + 1];
    g_sl0[b][n] = make_float2(sok ? sx : -1e18f, sy);
    g_sok0[b][n] = sok ? 1 : 0;
    g_skey[b][n] = sok ? morton_key(sx, sy) : 256;
    g_v2[b][n] = 0.0f;
    g_ev[b][n] = 1.0f;

    bool tok = read_mask(tmask, i, sf[1]);
    float tx = tlocs[2 * i], ty = tlocs[2 * i + 1];
    g_tl0[b][n] = make_float2(tok ? tx : 1e18f, ty);
    g_tkey[b][n] = tok ? morton_key(tx, ty) : 256;
}

// ---------------- stable counting sort + scatter + chunk bboxes ---------------
// grid (2, Bz); block 256 = 8 warps; warp w owns elements [w*512, w*512+512)
__global__ __launch_bounds__(256) void sort_scatter_kernel() {
    __shared__ int hist[8][257];
    __shared__ int cellbase[258];
    __shared__ unsigned short ranks[4096];
    const int side = blockIdx.x, b = blockIdx.y, tid = threadIdx.x;
    const int warp = tid >> 5, lane = tid & 31;
    const unsigned FULL = 0xffffffffu;

    for (int i = tid; i < 8 * 257; i += 256) (&hist[0][0])[i] = 0;
    __syncthreads();

    #pragma unroll
    for (int r = 0; r < 16; r++) {
        int i = warp * 512 + r * 32 + lane;
        int cell = side ? g_skey[b][i] : g_tkey[b][i];
        unsigned peers = __match_any_sync(FULL, cell);
        int leader = __ffs(peers) - 1;
        int rankin = __popc(peers & ((1u << lane) - 1u));
        int old = 0;
        if (lane == leader) old = atomicAdd(&hist[warp][cell], __popc(peers));
        old = __shfl_sync(FULL, old, leader);
        ranks[i] = (unsigned short)(old + rankin);
    }
    __syncthreads();

    for (int c = tid; c < 257; c += 256) {
        int run = 0;
        #pragma unroll
        for (int w = 0; w < 8; w++) {
            int t = hist[w][c];
            hist[w][c] = run;
            run += t;
        }
        cellbase[c + 1] = run;
    }
    __syncthreads();
    if (tid == 0) {
        cellbase[0] = 0;
        for (int c = 1; c <= 257; c++) cellbase[c] += cellbase[c - 1];
    }
    __syncthreads();

    #pragma unroll
    for (int r = 0; r < 16; r++) {
        int i = warp * 512 + r * 32 + lane;
        int cell = side ? g_skey[b][i] : g_tkey[b][i];
        int pos = cellbase[cell] + hist[warp][cell] + (int)ranks[i];
        if (side) {
            float2 p = g_sl0[b][i];
            g_sv4[b][pos] = make_float4(p.x, p.y, 0.0f, 0.0f);
            g_sok[b][pos] = g_sok0[b][i];
            g_sperm[b][pos] = i;
        } else {
            float2 p = g_tl0[b][i];
            g_tu4[b][pos] = make_float4(p.x, p.y, 0.0f, 0.0f);
            g_tperm[b][pos] = i;
        }
    }
    __syncthreads();

    for (int i = tid; i < 4096; i += 256) {
        float4 p4 = side ? g_sv4[b][i] : g_tu4[b][i];
        float mnx = p4.x, mxx = p4.x, mny = p4.y, mxy = p4.y;
        #pragma unroll
        for (int off = 16; off; off >>= 1) {
            mnx = fminf(mnx, __shfl_xor_sync(FULL, mnx, off));
            mxx = fmaxf(mxx, __shfl_xor_sync(FULL, mxx, off));
            mny = fminf(mny, __shfl_xor_sync(FULL, mny, off));
            mxy = fmaxf(mxy, __shfl_xor_sync(FULL, mxy, off));
        }
        if (lane == 0) {
            int chunk = i >> 5;
            float4 bb = make_float4(mnx, mny, mxx, mxy);
            if (side) g_sbb[b][chunk] = bb; else g_tbb[b][chunk] = bb;
        }
    }
}

// ---------------- build padded CSR (cols + K f32) once -------------------------
__global__ __launch_bounds__(256) void csr_build() {
    const int b = blockIdx.y, side = blockIdx.z;
    const int warp = threadIdx.x >> 5, lane = threadIdx.x & 31;
    const int row = blockIdx.x * 8 + warp;
    const unsigned FULL = 0xffffffffu;
    const float NEG_INV2 = c_NEG_INV2;

    float4 rp = (side == 0) ? g_tu4[b][row] : g_sv4[b][row];
    const float4* opp = (side == 0) ? g_sv4[b] : g_tu4[b];
    const float4* bb  = (side == 0) ? g_sbb[b] : g_tbb[b];
    unsigned short* cseg = ((side == 0) ? g_colT[b] : g_colS[b]) + (size_t)row * RSTRIDE;
    float*          vseg = ((side == 0) ? g_valT[b] : g_valS[b]) + (size_t)row * RSTRIDE;

    int cnt = 0;
    #pragma unroll
    for (int t = 0; t < 4; t++) {
        int c = t * 32 + lane;
        float4 cb = bb[c];
        float ddx = fmaxf(fmaxf(cb.x - rp.x, rp.x - cb.z), 0.0f);
        float ddy = fmaxf(fmaxf(cb.y - rp.y, rp.y - cb.w), 0.0f);
        bool inc = (ddx * ddx + ddy * ddy < 0.0401f);
        unsigned mask = __ballot_sync(FULL, inc);
        while (mask) {
            int chunk = t * 32 + (__ffs(mask) - 1);
            mask &= mask - 1;
            int col = chunk * 32 + lane;
            float4 q = opp[col];
            float dx = __fadd_rn(rp.x, -q.x);
            float dy = __fadd_rn(rp.y, -q.y);
            float d2 = __fadd_rn(__fmul_rn(dx, dx), __fmul_rn(dy, dy));
            bool valid = (d2 < 0.04f);
            unsigned vm = __ballot_sync(FULL, valid);
            if (valid) {
                int slot = cnt + __popc(vm & ((1u << lane) - 1u));
                if (slot < RSTRIDE) {
                    cseg[slot] = (unsigned short)col;
                    vseg[slot] = exp2f(__fmul_rn(d2, NEG_INV2));
                }
            }
            cnt += __popc(vm);
        }
    }
    if (lane == 0) {
        cnt = cnt > RSTRIDE ? RSTRIDE : cnt;
        if (side == 0) { g_nnzT[b][row] = cnt; g_has[b][row] = (cnt > 0) ? 1 : 0; }
        else           { g_nnzS[b][row] = cnt; }
    }
}

// ---------------- LSE pass: FMA stream over SoA CSR (R9 form) -----------------
template <int MODE>
__global__ __launch_bounds__(256) void lse_kernel(int iter) {
    const int b = blockIdx.y;
    const int warp = threadIdx.x >> 5, lane = threadIdx.x & 31;
    const int row = blockIdx.x * 8 + warp;
    const unsigned FULL = 0xffffffffu;

    const unsigned short* cseg = ((MODE == 0) ? g_colT[b] : g_colS[b]) + (size_t)row * RSTRIDE;
    const float*          vseg = ((MODE == 0) ? g_valT[b] : g_valS[b]) + (size_t)row * RSTRIDE;
    const float*          ed   = (MODE == 0) ? g_ev[b] : g_eu[b];
    const int cnt = (MODE == 0) ? g_nnzT[b][row] : g_nnzS[b][row];

    float s0 = 0.0f, s1 = 0.0f;
    int i = 2 * lane;
    for (; i + 1 < cnt; i += 64) {
        unsigned cc = *(const unsigned*)(cseg + i);
        float2 kk = *(const float2*)(vseg + i);
        s0 = __fmaf_rn(kk.x, ed[cc & 0xFFFFu], s0);
        s1 = __fmaf_rn(kk.y, ed[cc >> 16], s1);
    }
    if (i < cnt) s0 = __fmaf_rn(vseg[i], ed[cseg[i]], s0);

    float s = s0 + s1;
    #pragma unroll
    for (int off = 16; off; off >>= 1) s += __shfl_xor_sync(FULL, s, off);

    if (lane == 0) {
        if (MODE == 0) {
            float tot = s + ((iter > 0) ? (float)g_cnt0v[(iter - 1) * Bz + b] : 0.0f);
            float u2;
            if (tot > 0.0f) u2 = -log2f(tot);
            else { u2 = BIG2; atomicAdd(&g_cnt0u[iter * Bz + b], 1); }
            g_u2[b][row] = u2;
            g_eu[b][row] = (tot > 0.0f) ? exp2f(u2) : 1.0f;
        } else {
            float tot = s + (float)g_cnt0u[iter * Bz + b];
            bool sok = g_sok[b][row] != 0;
            float v2;
            if (tot > 0.0f) v2 = -log2f(tot);
            else { v2 = BIG2; if (sok) atomicAdd(&g_cnt0v[iter * Bz + b], 1); }
            v2 = sok ? v2 : 0.0f;
            g_v2[b][row] = v2;
            g_ev[b][row] = (tot > 0.0f || !sok) ? exp2f(v2) : 1.0f;
        }
    }
}

// ---------------- feats f32 [b][orig n][c] -> fp16 [b][c][sorted n] ----------
__global__ void feats_transpose(const float* __restrict__ f) {
    __shared__ float tile[32][33];
    int b = blockIdx.z;
    int n0 = blockIdx.x * 32, c0 = blockIdx.y * 32;
    int tx = threadIdx.x, ty = threadIdx.y;
    #pragma unroll
    for (int j = 0; j < 4; j++) {
        int n = n0 + ty + j * 8;
        int on = g_sperm[b][n];
        tile[ty + j * 8][tx] = f[((b * Nn + on) * Cc) + (c0 + tx)];
    }
    __syncthreads();
    #pragma unroll
    for (int j = 0; j < 4; j++) {
        int c = c0 + ty + j * 8;
        g_fT[b][c][n0 + tx] = __float2half(tile[tx][ty + j * 8]);
    }
}

// ---------------- fused attn-recompute GEMM: pipeline + per-warp skip --------
__device__ __forceinline__ void mma16816(float& c0, float& c1, float& c2, float& c3,
                                         unsigned a0, unsigned a1, unsigned a2, unsigned a3,
                                         unsigned b0, unsigned b1) {
    asm volatile(
        "mma.sync.aligned.m16n8k16.row.col.f32.f16.f16.f32 "
        "{%0,%1,%2,%3}, {%4,%5,%6,%7}, {%8,%9}, {%0,%1,%2,%3};\n"
        : "+f"(c0), "+f"(c1), "+f"(c2), "+f"(c3)
        : "r"(a0), "r"(a1), "r"(a2), "r"(a3), "r"(b0), "r"(b1));
}

__device__ __forceinline__ float attn_val(float txx, float tyy, float uu2, float4 q) {
    float dx = __fadd_rn(txx, -q.x);
    float dy = __fadd_rn(tyy, -q.y);
    float d2 = __fadd_rn(__fmul_rn(dx, dx), __fmul_rn(dy, dy));
    if (d2 < 0.04f)
        return exp2f(__fadd_rn(__fmaf_rn(d2, c_NEG_INV2, uu2), q.z));
    return 0.0f;
}

__device__ __forceinline__ unsigned pack2(float x, float y) {
    __half2 h = __floats2half2_rn(x, y);
    return *reinterpret_cast<unsigned*>(&h);
}

#define GBM 64
#define GBC 128
#define GBK 64
#define SBSTRIDE 72

// 256 threads = 8 warps = 4 m-groups x 2 c-halves; grid (64, 2, Bz)
__global__ __launch_bounds__(256) void gemm_kernel(float* __restrict__ out) {
    const int b  = blockIdx.z;
    const int m0 = blockIdx.x * GBM;
    const int c0 = blockIdx.y * GBC;
    const int warp = threadIdx.x >> 5, lane = threadIdx.x & 31;
    const int mg = warp >> 1, chalf = warp & 1;
    const int gid = lane >> 2, tig = lane & 3;

    __shared__ __align__(16) __half sB[2][GBC][SBSTRIDE];
    __shared__ __align__(16) float4 sS[2][GBK];
    __shared__ unsigned char sCL[64];
    __shared__ int sCN;

    if (warp == 0) {
        float tmnx, tmxx, tmny, tmxy;
        {
            float4 b0 = g_tbb[b][(m0 >> 5) + 0], b1 = g_tbb[b][(m0 >> 5) + 1];
            tmnx = fminf(b0.x, b1.x); tmny = fminf(b0.y, b1.y);
            tmxx = fmaxf(b0.z, b1.z); tmxy = fmaxf(b0.w, b1.w);
        }
        int base = 0;
        #pragma unroll
        for (int t = 0; t < 2; t++) {
            int kc = t * 32 + lane;
            float4 s0 = g_sbb[b][kc * 2 + 0], s1 = g_sbb[b][kc * 2 + 1];
            float smnx = fminf(s0.x, s1.x), smny = fminf(s0.y, s1.y);
            float smxx = fmaxf(s0.z, s1.z), smxy = fmaxf(s0.w, s1.w);
            float ddx = fmaxf(fmaxf(smnx - tmxx, tmnx - smxx), 0.0f);
            float ddy = fmaxf(fmaxf(smny - tmxy, tmny - smxy), 0.0f);
            bool inc = (ddx * ddx + ddy * ddy < 0.0401f);
            unsigned mask = __ballot_sync(0xffffffffu, inc);
            if (inc) sCL[base + __popc(mask & ((1u << lane) - 1u))] = (unsigned char)kc;
            base += __popc(mask);
        }
        if (lane == 0) sCN = base;
    }

    const int rlo = m0 + mg * 16 + gid;
    const int rhi = rlo + 8;
    float4 plo = g_tu4[b][rlo]; plo.z = g_u2[b][rlo];
    float4 phi = g_tu4[b][rhi]; phi.z = g_u2[b][rhi];
    const bool haslo = g_has[b][rlo] != 0;
    const bool hashi = g_has[b][rhi] != 0;

    // per-warp bbox over its 16 m-rows (lanes collectively hold all 16)
    float wmnx = fminf(plo.x, phi.x), wmxx = fmaxf(plo.x, phi.x);
    float wmny = fminf(plo.y, phi.y), wmxy = fmaxf(plo.y, phi.y);
    #pragma unroll
    for (int off = 16; off; off >>= 1) {
        wmnx = fminf(wmnx, __shfl_xor_sync(0xffffffffu, wmnx, off));
        wmxx = fmaxf(wmxx, __shfl_xor_sync(0xffffffffu, wmxx, off));
        wmny = fminf(wmny, __shfl_xor_sync(0xffffffffu, wmny, off));
        wmxy = fmaxf(wmxy, __shfl_xor_sync(0xffffffffu, wmxy, off));
    }

    float acc[8][4];
    #pragma unroll
    for (int j = 0; j < 8; j++) {
        acc[j][0] = 0.f; acc[j][1] = 0.f; acc[j][2] = 0.f; acc[j][3] = 0.f;
    }

    __syncthreads();
    const int ccount = sCN;

    #define STAGE(buf, kc) do {                                                   \
        int n0_ = (kc) * GBK;                                                     \
        int idx_ = threadIdx.x;                                                   \
        _Pragma("unroll")                                                         \
        for (int t_ = 0; t_ < 4; t_++, idx_ += 256) {                             \
            int row_ = idx_ >> 3, ch8_ = idx_ & 7;                                \
            const uint4* src_ = reinterpret_cast<const uint4*>(&g_fT[b][c0 + row_][n0_]) + ch8_; \
            *reinterpret_cast<uint4*>(&sB[buf][row_][ch8_ * 8]) = *src_;          \
        }                                                                         \
        if (threadIdx.x < GBK) {                                                  \
            int n_ = n0_ + threadIdx.x;                                           \
            float4 p_ = g_sv4[b][n_];                                             \
            p_.z = g_v2[b][n_];                                                   \
            sS[buf][threadIdx.x] = p_;                                            \
        }                                                                         \
    } while (0)

    if (ccount > 0) STAGE(0, (int)sCL[0]);

    for (int ci = 0; ci < ccount; ci++) {
        const int cur = ci & 1;
        const int kc = (int)sCL[ci];
        __syncthreads();
        if (ci + 1 < ccount) STAGE(cur ^ 1, (int)sCL[ci + 1]);

        // per-warp skip: chunk bbox vs this warp's 16-row bbox (bit-exact zeros)
        {
            float4 s0 = g_sbb[b][kc * 2 + 0], s1 = g_sbb[b][kc * 2 + 1];
            float smnx = fminf(s0.x, s1.x), smny = fminf(s0.y, s1.y);
            float smxx = fmaxf(s0.z, s1.z), smxy = fmaxf(s0.w, s1.w);
            float ddx = fmaxf(fmaxf(smnx - wmxx, wmnx - smxx), 0.0f);
            float ddy = fmaxf(fmaxf(smny - wmxy, wmny - smxy), 0.0f);
            if (ddx * ddx + ddy * ddy >= 0.0401f) continue;
        }

        #pragma unroll
        for (int kf = 0; kf < 4; kf++) {
            const int kb = kf * 16 + 2 * tig;
            float4 qa = sS[cur][kb];
            float4 qb = sS[cur][kb + 1];
            float4 qc = sS[cur][kb + 8];
            float4 qd = sS[cur][kb + 9];

            unsigned a0 = pack2(attn_val(plo.x, plo.y, plo.z, qa), attn_val(plo.x, plo.y, plo.z, qb));
            unsigned a1 = pack2(attn_val(phi.x, phi.y, phi.z, qa), attn_val(phi.x, phi.y, phi.z, qb));
            unsigned a2 = pack2(attn_val(plo.x, plo.y, plo.z, qc), attn_val(plo.x, plo.y, plo.z, qd));
            unsigned a3 = pack2(attn_val(phi.x, phi.y, phi.z, qc), attn_val(phi.x, phi.y, phi.z, qd));

            #pragma unroll
            for (int j = 0; j < 8; j++) {
                const __half* brow = &sB[cur][chalf * 64 + j * 8 + gid][kf * 16 + 2 * tig];
                unsigned b0 = *reinterpret_cast<const unsigned*>(brow);
                unsigned b1 = *reinterpret_cast<const unsigned*>(brow + 8);
                mma16816(acc[j][0], acc[j][1], acc[j][2], acc[j][3],
                         a0, a1, a2, a3, b0, b1);
            }
        }
    }
    #undef STAGE

    const int orlo = g_tperm[b][rlo];
    const int orhi = g_tperm[b][rhi];
    #pragma unroll
    for (int j = 0; j < 8; j++) {
        int c = c0 + chalf * 64 + j * 8 + 2 * tig;
        float2 vlo = haslo ? make_float2(acc[j][0], acc[j][1]) : make_float2(0.f, 0.f);
        float2 vhi = hashi ? make_float2(acc[j][2], acc[j][3]) : make_float2(0.f, 0.f);
        *reinterpret_cast<float2*>(&out[((b * Mm + orlo) * Cc) + c]) = vlo;
        *reinterpret_cast<float2*>(&out[((b * Mm + orhi) * Cc) + c]) = vhi;
    }
}

// ------------------------------- launch ---------------------------------------
extern "C" void kernel_launch(void* const* d_in, const int* in_sizes, int n_in,
                              void* d_out, int out_size) {
    const float* feats = (const float*)d_in[0];
    const float* slocs = (const float*)d_in[1];
    const float* tlocs = (const float*)d_in[2];
    const void*  smask = d_in[3];
    const void*  tmask = d_in[4];
    float* out = (float*)d_out;

    prep_kernel<<<(Bz * Nn + 255) / 256, 256>>>(slocs, tlocs, smask, tmask);   // 1
    sort_scatter_kernel<<<dim3(2, Bz), 256>>>();                                // 2
    feats_transpose<<<dim3(Nn / 32, Cc / 32, Bz), dim3(32, 8)>>>(feats);        // 3
    csr_build<<<dim3(4096 / 8, Bz, 2), 256>>>();                                // 4 <- profiled

    for (int it = 0; it < 3; it++) {
        lse_kernel<0><<<dim3(4096 / 8, Bz), 256>>>(it);
        lse_kernel<1><<<dim3(4096 / 8, Bz), 256>>>(it);
    }

    gemm_kernel<<<dim3(Mm / GBM, 2, Bz), 256>>>(out);
}